// round 7
// baseline (speedup 1.0000x reference)
#include <cuda_runtime.h>
#include <cuda_bf16.h>
#include <math.h>
#include <stdint.h>

#define N_NODES 50000
#define N_EDGES 800000
#define N_GRAPHS 64
#define HEADS 4
#define IN_CH 128
#define HID_CH 64
#define OUT_CH 32
#define CH1 (HEADS*HID_CH)   // 256
#define CH2 (HEADS*OUT_CH)   // 128

#define SCAN_B 1024
#define NB ((N_NODES + SCAN_B - 1) / SCAN_B)   // 49

// ---------------- scratch (device globals) ----------------------------------
__device__ float g_h1[N_NODES * CH1];
__device__ float g_h1gat[N_NODES * CH1];
__device__ float g_h2[N_NODES * CH2];
__device__ float g_s1[N_NODES * HEADS], g_d1[N_NODES * HEADS];
__device__ float g_s2[N_NODES * HEADS], g_d2[N_NODES * HEADS];
__device__ int   g_cnt[N_NODES];
__device__ int   g_cursor[N_NODES];
__device__ int   g_incl[N_NODES];
__device__ int   g_indptr[N_NODES + 1];
__device__ int   g_esrc[N_EDGES];
__device__ int   g_blocksums[NB];
__device__ float g_sums[N_GRAPHS * CH2];
__device__ int   g_counts[N_GRAPHS];

__device__ __forceinline__ float lrelu(float x) {
    return x > 0.f ? x : 0.2f * x;
}

// ---------------- zero scratch ----------------------------------------------
__global__ void zero_kernel() {
    int i = blockIdx.x * blockDim.x + threadIdx.x;
    if (i < N_NODES) { g_cnt[i] = 0; g_cursor[i] = 0; }
    if (i < N_GRAPHS * CH2) g_sums[i] = 0.f;
    if (i < N_GRAPHS) g_counts[i] = 0;
}

// ---------------- CSR build --------------------------------------------------
__global__ void count_kernel(const int* __restrict__ ei) {
    int e = blockIdx.x * blockDim.x + threadIdx.x;
    if (e < N_EDGES) atomicAdd(&g_cnt[ei[N_EDGES + e]], 1);
}

__global__ void scan1_kernel() {
    __shared__ int sh[SCAN_B];
    int i = blockIdx.x * SCAN_B + threadIdx.x;
    int v = (i < N_NODES) ? g_cnt[i] : 0;
    sh[threadIdx.x] = v;
    __syncthreads();
    #pragma unroll
    for (int off = 1; off < SCAN_B; off <<= 1) {
        int t = (threadIdx.x >= off) ? sh[threadIdx.x - off] : 0;
        __syncthreads();
        sh[threadIdx.x] += t;
        __syncthreads();
    }
    if (i < N_NODES) g_incl[i] = sh[threadIdx.x];
    if (threadIdx.x == SCAN_B - 1) g_blocksums[blockIdx.x] = sh[SCAN_B - 1];
}

__global__ void scan2_kernel() {
    __shared__ int sh[64];
    int t = threadIdx.x;
    int v = (t < NB) ? g_blocksums[t] : 0;
    sh[t] = v;
    __syncthreads();
    #pragma unroll
    for (int off = 1; off < 64; off <<= 1) {
        int u = (t >= off) ? sh[t - off] : 0;
        __syncthreads();
        sh[t] += u;
        __syncthreads();
    }
    if (t < NB) g_blocksums[t] = sh[t] - v;   // exclusive
}

__global__ void scan3_kernel() {
    int i = blockIdx.x * blockDim.x + threadIdx.x;
    if (i < N_NODES) g_indptr[i + 1] = g_incl[i] + g_blocksums[i / SCAN_B];
    if (i == 0) g_indptr[0] = 0;
}

__global__ void scatter_kernel(const int* __restrict__ ei) {
    int e = blockIdx.x * blockDim.x + threadIdx.x;
    if (e < N_EDGES) {
        int s = ei[e];
        int d = ei[N_EDGES + e];
        int pos = g_indptr[d] + atomicAdd(&g_cursor[d], 1);
        g_esrc[pos] = s;
    }
}

// ---------------- tf32 tensor-core GEMM --------------------------------------
#define BM 128
#define BN 64
#define BK 32
#define ASTRIDE 36
#define BSTRIDE 72

__device__ __forceinline__ float cvt_tf32(float x) {
    uint32_t r;
    asm("cvt.rna.tf32.f32 %0, %1;" : "=r"(r) : "f"(x));
    return __uint_as_float(r);
}

__device__ __forceinline__ void mma_tf32(float c[4], const float a[4], const float b[2]) {
    asm volatile(
        "mma.sync.aligned.m16n8k8.row.col.f32.tf32.tf32.f32 "
        "{%0,%1,%2,%3}, {%4,%5,%6,%7}, {%8,%9}, {%0,%1,%2,%3};"
        : "+f"(c[0]), "+f"(c[1]), "+f"(c[2]), "+f"(c[3])
        : "r"(__float_as_uint(a[0])), "r"(__float_as_uint(a[1])),
          "r"(__float_as_uint(a[2])), "r"(__float_as_uint(a[3])),
          "r"(__float_as_uint(b[0])), "r"(__float_as_uint(b[1])));
}

template <int LAYER>
__global__ __launch_bounds__(256) void gemm_tf32_kernel(
    const float* __restrict__ Ain, const float* __restrict__ B)
{
    constexpr int N = (LAYER == 1) ? CH1 : CH2;
    constexpr int K = (LAYER == 1) ? IN_CH : CH1;
    const int M = N_NODES;
    const float* A = (LAYER == 1) ? Ain : g_h1gat;
    float* C = (LAYER == 1) ? g_h1 : g_h2;

    __shared__ float As[BM][ASTRIDE];
    __shared__ float Bs[BK][BSTRIDE];

    int tid = threadIdx.x;
    int brow = blockIdx.y * BM;
    int bcol = blockIdx.x * BN;
    int wid = tid >> 5, lane = tid & 31;
    int wm = wid & 3, wn = wid >> 2;
    int grp = lane >> 2;
    int q = lane & 3;

    int ar = tid >> 3;
    int ac4 = (tid & 7) << 2;
    int bc4 = (tid & 15) << 2;
    int br0 = tid >> 4;

    float4 ra[4], rb[2];

    auto load_regs = [&](int k0) {
        #pragma unroll
        for (int i = 0; i < 4; i++) {
            int gr = brow + ar + i * 32;
            ra[i] = make_float4(0.f, 0.f, 0.f, 0.f);
            if (gr < M) ra[i] = *(const float4*)&A[(size_t)gr * K + k0 + ac4];
        }
        #pragma unroll
        for (int i = 0; i < 2; i++) {
            int r = br0 + i * 16;
            rb[i] = *(const float4*)&B[(size_t)(k0 + r) * N + bcol + bc4];
        }
    };
    auto store_smem = [&]() {
        #pragma unroll
        for (int i = 0; i < 4; i++) {
            int r = ar + i * 32;
            As[r][ac4 + 0] = cvt_tf32(ra[i].x);
            As[r][ac4 + 1] = cvt_tf32(ra[i].y);
            As[r][ac4 + 2] = cvt_tf32(ra[i].z);
            As[r][ac4 + 3] = cvt_tf32(ra[i].w);
        }
        #pragma unroll
        for (int i = 0; i < 2; i++) {
            int r = br0 + i * 16;
            Bs[r][bc4 + 0] = cvt_tf32(rb[i].x);
            Bs[r][bc4 + 1] = cvt_tf32(rb[i].y);
            Bs[r][bc4 + 2] = cvt_tf32(rb[i].z);
            Bs[r][bc4 + 3] = cvt_tf32(rb[i].w);
        }
    };

    float c[2][4][4];
    #pragma unroll
    for (int mt = 0; mt < 2; mt++)
        #pragma unroll
        for (int nt = 0; nt < 4; nt++)
            #pragma unroll
            for (int r = 0; r < 4; r++) c[mt][nt][r] = 0.f;

    load_regs(0);
    store_smem();
    __syncthreads();

    for (int k0 = 0; k0 < K; k0 += BK) {
        bool has_next = (k0 + BK) < K;
        if (has_next) load_regs(k0 + BK);

        #pragma unroll
        for (int ks = 0; ks < BK / 8; ks++) {
            int kk = ks * 8;
            float a[2][4], b[4][2];
            #pragma unroll
            for (int mt = 0; mt < 2; mt++) {
                int mb = wm * 32 + mt * 16 + grp;
                a[mt][0] = As[mb][kk + q];
                a[mt][1] = As[mb + 8][kk + q];
                a[mt][2] = As[mb][kk + q + 4];
                a[mt][3] = As[mb + 8][kk + q + 4];
            }
            #pragma unroll
            for (int nt = 0; nt < 4; nt++) {
                int nb = wn * 32 + nt * 8 + grp;
                b[nt][0] = Bs[kk + q][nb];
                b[nt][1] = Bs[kk + q + 4][nb];
            }
            #pragma unroll
            for (int mt = 0; mt < 2; mt++)
                #pragma unroll
                for (int nt = 0; nt < 4; nt++)
                    mma_tf32(c[mt][nt], a[mt], b[nt]);
        }
        __syncthreads();
        if (has_next) {
            store_smem();
            __syncthreads();
        }
    }

    #pragma unroll
    for (int mt = 0; mt < 2; mt++) {
        int rg0 = brow + wm * 32 + mt * 16 + grp;
        #pragma unroll
        for (int nt = 0; nt < 4; nt++) {
            int cg = bcol + wn * 32 + nt * 8 + q * 2;
            if (rg0 < M) {
                C[(size_t)rg0 * N + cg]     = c[mt][nt][0];
                C[(size_t)rg0 * N + cg + 1] = c[mt][nt][1];
            }
            if (rg0 + 8 < M) {
                C[(size_t)(rg0 + 8) * N + cg]     = c[mt][nt][2];
                C[(size_t)(rg0 + 8) * N + cg + 1] = c[mt][nt][3];
            }
        }
    }
}

// ---------------- per-(node,head) attention terms s,d ------------------------
template <int HC, int LAYER>
__global__ void sd_kernel(const float* __restrict__ a_src,
                          const float* __restrict__ a_dst)
{
    int gw = blockIdx.x * (blockDim.x >> 5) + (threadIdx.x >> 5);
    int lane = threadIdx.x & 31;
    if (gw >= N_NODES * HEADS) return;
    int n = gw >> 2;
    int hh = gw & 3;
    const int CH = HEADS * HC;
    const float* h = (LAYER == 1) ? g_h1 : g_h2;
    float sv = 0.f, dv = 0.f;
    #pragma unroll
    for (int c = lane; c < HC; c += 32) {
        float hv = h[(size_t)n * CH + hh * HC + c];
        sv += hv * a_src[hh * HC + c];
        dv += hv * a_dst[hh * HC + c];
    }
    #pragma unroll
    for (int off = 16; off > 0; off >>= 1) {
        sv += __shfl_down_sync(0xffffffff, sv, off);
        dv += __shfl_down_sync(0xffffffff, dv, off);
    }
    if (lane == 0) {
        if (LAYER == 1) { g_s1[gw] = sv; g_d1[gw] = dv; }
        else            { g_s2[gw] = sv; g_d2[gw] = dv; }
    }
}

// ---------------- fused GAT softmax-aggregate v4 ------------------------------
// Block per node, 256 threads split into NG edge-groups; each thread owns 4
// channels (float4 gathers). No segment-max (mathematically redundant here).
// LAYER==2 additionally fuses the global mean-pool accumulation (atomics).
#define CHUNK 128
#define AGG_T 256
template <int HC, int LAYER>
__global__ __launch_bounds__(AGG_T) void agg_kernel(const float* __restrict__ bias,
                                                    const int* __restrict__ batch)
{
    constexpr int CH = HEADS * HC;       // 256 / 128
    constexpr int TPG = CH / 4;          // 64 / 32 threads per edge-group
    constexpr int NG = AGG_T / TPG;      // 4 / 8 groups

    __shared__ int   s_src[CHUNK];
    __shared__ float s_w[CHUNK * HEADS];
    __shared__ float s_acc[NG * CH];
    __shared__ float s_den[NG * HEADS];

    int n = blockIdx.x;
    int tid = threadIdx.x;
    int g = tid / TPG;
    int l = tid % TPG;
    int c0 = l * 4;
    int hh = c0 / HC;

    const float* h   = (LAYER == 1) ? g_h1 : g_h2;
    const float* s   = (LAYER == 1) ? g_s1 : g_s2;
    const float* d   = (LAYER == 1) ? g_d1 : g_d2;

    int beg = g_indptr[n], end = g_indptr[n + 1];

    float4 dn4 = *(const float4*)&d[n * 4];
    float4 ss4 = *(const float4*)&s[n * 4];
    const float* dnp = (const float*)&dn4;
    const float* ssp = (const float*)&ss4;

    float4 acc = make_float4(0.f, 0.f, 0.f, 0.f);
    float denom = 0.f;

    // self-loop handled by group 0
    if (g == 0) {
        float w_self = __expf(lrelu(ssp[hh] + dnp[hh]));
        float4 hv = *(const float4*)&h[(size_t)n * CH + c0];
        acc.x = w_self * hv.x;
        acc.y = w_self * hv.y;
        acc.z = w_self * hv.z;
        acc.w = w_self * hv.w;
        denom = w_self;
    }

    for (int base = beg; base < end; base += CHUNK) {
        int cnt = min(CHUNK, end - base);
        __syncthreads();
        if (tid < cnt) {
            int src = g_esrc[base + tid];
            float4 s4 = *(const float4*)&s[src * 4];
            float4 w4;
            w4.x = __expf(lrelu(s4.x + dn4.x));
            w4.y = __expf(lrelu(s4.y + dn4.y));
            w4.z = __expf(lrelu(s4.z + dn4.z));
            w4.w = __expf(lrelu(s4.w + dn4.w));
            s_src[tid] = src;
            *(float4*)&s_w[tid * 4] = w4;
        }
        __syncthreads();
        for (int e = g; e < cnt; e += NG) {
            int src = s_src[e];
            float w = s_w[e * 4 + hh];
            float4 hv = *(const float4*)&h[(size_t)src * CH + c0];
            denom += w;
            acc.x += w * hv.x;
            acc.y += w * hv.y;
            acc.z += w * hv.z;
            acc.w += w * hv.w;
        }
    }

    // cross-group reduction
    *(float4*)&s_acc[g * CH + c0] = acc;
    if ((c0 % HC) == 0) s_den[g * HEADS + hh] = denom;
    __syncthreads();

    if (tid < TPG) {
        float4 a = *(float4*)&s_acc[c0];
        float den = s_den[hh];
        #pragma unroll
        for (int ng = 1; ng < NG; ng++) {
            float4 b = *(float4*)&s_acc[ng * CH + c0];
            a.x += b.x; a.y += b.y; a.z += b.z; a.w += b.w;
            den += s_den[ng * HEADS + hh];
        }
        den += 1e-16f;
        float4 bi = *(const float4*)&bias[c0];
        float v0 = fmaxf(a.x / den + bi.x, 0.f);
        float v1 = fmaxf(a.y / den + bi.y, 0.f);
        float v2 = fmaxf(a.z / den + bi.z, 0.f);
        float v3 = fmaxf(a.w / den + bi.w, 0.f);
        if (LAYER == 1) {
            float4 v = make_float4(v0, v1, v2, v3);
            *(float4*)&g_h1gat[(size_t)n * CH + c0] = v;
        } else {
            int gb = batch[n];
            atomicAdd(&g_sums[gb * CH2 + c0 + 0], v0);
            atomicAdd(&g_sums[gb * CH2 + c0 + 1], v1);
            atomicAdd(&g_sums[gb * CH2 + c0 + 2], v2);
            atomicAdd(&g_sums[gb * CH2 + c0 + 3], v3);
            if (tid == 0) atomicAdd(&g_counts[gb], 1);
        }
    }
}

// ---------------- final logits + softmax --------------------------------------
__global__ void final_kernel(const float* __restrict__ Wout,
                             const float* __restrict__ bout,
                             float* __restrict__ out)
{
    int g = threadIdx.x;
    if (g >= N_GRAPHS) return;
    float cnt = fmaxf((float)g_counts[g], 1.0f);
    float l0 = bout[0], l1 = bout[1];
    for (int c = 0; c < CH2; c++) {
        float p = g_sums[g * CH2 + c] / cnt;
        l0 += p * Wout[c * 2 + 0];
        l1 += p * Wout[c * 2 + 1];
    }
    float mx = fmaxf(l0, l1);
    float e0 = expf(l0 - mx), e1 = expf(l1 - mx);
    float inv = 1.f / (e0 + e1);
    out[g * 2 + 0] = e0 * inv;
    out[g * 2 + 1] = e1 * inv;
}

// ---------------- launch -------------------------------------------------------
extern "C" void kernel_launch(void* const* d_in, const int* in_sizes, int n_in,
                              void* d_out, int out_size) {
    const float* x      = (const float*)d_in[0];
    const int*   ei     = (const int*)d_in[1];
    const int*   batch  = (const int*)d_in[2];
    const float* W1     = (const float*)d_in[3];
    const float* a_src1 = (const float*)d_in[4];
    const float* a_dst1 = (const float*)d_in[5];
    const float* b1     = (const float*)d_in[6];
    const float* W2     = (const float*)d_in[7];
    const float* a_src2 = (const float*)d_in[8];
    const float* a_dst2 = (const float*)d_in[9];
    const float* b2     = (const float*)d_in[10];
    const float* Wout   = (const float*)d_in[11];
    const float* bout   = (const float*)d_in[12];
    float* out = (float*)d_out;

    zero_kernel<<<(N_NODES + 255) / 256, 256>>>();

    count_kernel<<<(N_EDGES + 255) / 256, 256>>>(ei);
    scan1_kernel<<<NB, SCAN_B>>>();
    scan2_kernel<<<1, 64>>>();
    scan3_kernel<<<(N_NODES + 255) / 256, 256>>>();
    scatter_kernel<<<(N_EDGES + 255) / 256, 256>>>(ei);

    {
        dim3 grid(CH1 / BN, (N_NODES + BM - 1) / BM);
        gemm_tf32_kernel<1><<<grid, 256>>>(x, W1);
    }
    sd_kernel<HID_CH, 1><<<(N_NODES * HEADS * 32 + 255) / 256, 256>>>(a_src1, a_dst1);
    agg_kernel<HID_CH, 1><<<N_NODES, AGG_T>>>(b1, batch);

    {
        dim3 grid(CH2 / BN, (N_NODES + BM - 1) / BM);
        gemm_tf32_kernel<2><<<grid, 256>>>(nullptr, W2);
    }
    sd_kernel<OUT_CH, 2><<<(N_NODES * HEADS * 32 + 255) / 256, 256>>>(a_src2, a_dst2);
    agg_kernel<OUT_CH, 2><<<N_NODES, AGG_T>>>(b2, batch);

    final_kernel<<<1, 64>>>(Wout, bout, out);
}

// round 8
// speedup vs baseline: 1.9610x; 1.9610x over previous
#include <cuda_runtime.h>
#include <cuda_bf16.h>
#include <math.h>
#include <stdint.h>

#define N_NODES 50000
#define N_EDGES 800000
#define N_GRAPHS 64
#define HEADS 4
#define IN_CH 128
#define HID_CH 64
#define OUT_CH 32
#define CH1 (HEADS*HID_CH)   // 256
#define CH2 (HEADS*OUT_CH)   // 128

#define SCAN_B 1024
#define NB ((N_NODES + SCAN_B - 1) / SCAN_B)   // 49

// ---------------- scratch (device globals) ----------------------------------
__device__ float g_h1[N_NODES * CH1];
__device__ float g_h1gat[N_NODES * CH1];
__device__ float g_h2[N_NODES * CH2];
__device__ float g_s1[N_NODES * HEADS], g_d1[N_NODES * HEADS];
__device__ float g_s2[N_NODES * HEADS], g_d2[N_NODES * HEADS];
__device__ int   g_cnt[N_NODES];
__device__ int   g_cursor[N_NODES];
__device__ int   g_incl[N_NODES];
__device__ int   g_indptr[N_NODES + 1];
__device__ int   g_esrc[N_EDGES];
__device__ int   g_blocksums[NB];
__device__ float g_sums[N_GRAPHS * CH2];
__device__ int   g_counts[N_GRAPHS];

__device__ __forceinline__ float lrelu(float x) {
    return x > 0.f ? x : 0.2f * x;
}

// ---------------- zero scratch ----------------------------------------------
__global__ void zero_kernel() {
    int i = blockIdx.x * blockDim.x + threadIdx.x;
    if (i < N_NODES) { g_cnt[i] = 0; g_cursor[i] = 0; }
    if (i < N_GRAPHS * CH2) g_sums[i] = 0.f;
    if (i < N_GRAPHS) g_counts[i] = 0;
}

// ---------------- CSR build --------------------------------------------------
__global__ void count_kernel(const int* __restrict__ ei) {
    int e = blockIdx.x * blockDim.x + threadIdx.x;
    if (e < N_EDGES) atomicAdd(&g_cnt[ei[N_EDGES + e]], 1);
}

__global__ void scan1_kernel() {
    __shared__ int sh[SCAN_B];
    int i = blockIdx.x * SCAN_B + threadIdx.x;
    int v = (i < N_NODES) ? g_cnt[i] : 0;
    sh[threadIdx.x] = v;
    __syncthreads();
    #pragma unroll
    for (int off = 1; off < SCAN_B; off <<= 1) {
        int t = (threadIdx.x >= off) ? sh[threadIdx.x - off] : 0;
        __syncthreads();
        sh[threadIdx.x] += t;
        __syncthreads();
    }
    if (i < N_NODES) g_incl[i] = sh[threadIdx.x];
    if (threadIdx.x == SCAN_B - 1) g_blocksums[blockIdx.x] = sh[SCAN_B - 1];
}

__global__ void scan2_kernel() {
    __shared__ int sh[64];
    int t = threadIdx.x;
    int v = (t < NB) ? g_blocksums[t] : 0;
    sh[t] = v;
    __syncthreads();
    #pragma unroll
    for (int off = 1; off < 64; off <<= 1) {
        int u = (t >= off) ? sh[t - off] : 0;
        __syncthreads();
        sh[t] += u;
        __syncthreads();
    }
    if (t < NB) g_blocksums[t] = sh[t] - v;   // exclusive
}

__global__ void scan3_kernel() {
    int i = blockIdx.x * blockDim.x + threadIdx.x;
    if (i < N_NODES) g_indptr[i + 1] = g_incl[i] + g_blocksums[i / SCAN_B];
    if (i == 0) g_indptr[0] = 0;
}

__global__ void scatter_kernel(const int* __restrict__ ei) {
    int e = blockIdx.x * blockDim.x + threadIdx.x;
    if (e < N_EDGES) {
        int s = ei[e];
        int d = ei[N_EDGES + e];
        int pos = g_indptr[d] + atomicAdd(&g_cursor[d], 1);
        g_esrc[pos] = s;
    }
}

// ---------------- tf32 tensor-core GEMM --------------------------------------
#define BM 128
#define BN 64
#define BK 32
#define ASTRIDE 36
#define BSTRIDE 72

__device__ __forceinline__ float cvt_tf32(float x) {
    uint32_t r;
    asm("cvt.rna.tf32.f32 %0, %1;" : "=r"(r) : "f"(x));
    return __uint_as_float(r);
}

__device__ __forceinline__ void mma_tf32(float c[4], const float a[4], const float b[2]) {
    asm volatile(
        "mma.sync.aligned.m16n8k8.row.col.f32.tf32.tf32.f32 "
        "{%0,%1,%2,%3}, {%4,%5,%6,%7}, {%8,%9}, {%0,%1,%2,%3};"
        : "+f"(c[0]), "+f"(c[1]), "+f"(c[2]), "+f"(c[3])
        : "r"(__float_as_uint(a[0])), "r"(__float_as_uint(a[1])),
          "r"(__float_as_uint(a[2])), "r"(__float_as_uint(a[3])),
          "r"(__float_as_uint(b[0])), "r"(__float_as_uint(b[1])));
}

template <int LAYER>
__global__ __launch_bounds__(256) void gemm_tf32_kernel(
    const float* __restrict__ Ain, const float* __restrict__ B)
{
    constexpr int N = (LAYER == 1) ? CH1 : CH2;
    constexpr int K = (LAYER == 1) ? IN_CH : CH1;
    const int M = N_NODES;
    const float* A = (LAYER == 1) ? Ain : g_h1gat;
    float* C = (LAYER == 1) ? g_h1 : g_h2;

    __shared__ float As[BM][ASTRIDE];
    __shared__ float Bs[BK][BSTRIDE];

    int tid = threadIdx.x;
    int brow = blockIdx.y * BM;
    int bcol = blockIdx.x * BN;
    int wid = tid >> 5, lane = tid & 31;
    int wm = wid & 3, wn = wid >> 2;
    int grp = lane >> 2;
    int q = lane & 3;

    int ar = tid >> 3;
    int ac4 = (tid & 7) << 2;
    int bc4 = (tid & 15) << 2;
    int br0 = tid >> 4;

    float4 ra[4], rb[2];

    auto load_regs = [&](int k0) {
        #pragma unroll
        for (int i = 0; i < 4; i++) {
            int gr = brow + ar + i * 32;
            ra[i] = make_float4(0.f, 0.f, 0.f, 0.f);
            if (gr < M) ra[i] = *(const float4*)&A[(size_t)gr * K + k0 + ac4];
        }
        #pragma unroll
        for (int i = 0; i < 2; i++) {
            int r = br0 + i * 16;
            rb[i] = *(const float4*)&B[(size_t)(k0 + r) * N + bcol + bc4];
        }
    };
    auto store_smem = [&]() {
        #pragma unroll
        for (int i = 0; i < 4; i++) {
            int r = ar + i * 32;
            As[r][ac4 + 0] = cvt_tf32(ra[i].x);
            As[r][ac4 + 1] = cvt_tf32(ra[i].y);
            As[r][ac4 + 2] = cvt_tf32(ra[i].z);
            As[r][ac4 + 3] = cvt_tf32(ra[i].w);
        }
        #pragma unroll
        for (int i = 0; i < 2; i++) {
            int r = br0 + i * 16;
            Bs[r][bc4 + 0] = cvt_tf32(rb[i].x);
            Bs[r][bc4 + 1] = cvt_tf32(rb[i].y);
            Bs[r][bc4 + 2] = cvt_tf32(rb[i].z);
            Bs[r][bc4 + 3] = cvt_tf32(rb[i].w);
        }
    };

    float c[2][4][4];
    #pragma unroll
    for (int mt = 0; mt < 2; mt++)
        #pragma unroll
        for (int nt = 0; nt < 4; nt++)
            #pragma unroll
            for (int r = 0; r < 4; r++) c[mt][nt][r] = 0.f;

    load_regs(0);
    store_smem();
    __syncthreads();

    for (int k0 = 0; k0 < K; k0 += BK) {
        bool has_next = (k0 + BK) < K;
        if (has_next) load_regs(k0 + BK);

        #pragma unroll
        for (int ks = 0; ks < BK / 8; ks++) {
            int kk = ks * 8;
            float a[2][4], b[4][2];
            #pragma unroll
            for (int mt = 0; mt < 2; mt++) {
                int mb = wm * 32 + mt * 16 + grp;
                a[mt][0] = As[mb][kk + q];
                a[mt][1] = As[mb + 8][kk + q];
                a[mt][2] = As[mb][kk + q + 4];
                a[mt][3] = As[mb + 8][kk + q + 4];
            }
            #pragma unroll
            for (int nt = 0; nt < 4; nt++) {
                int nb = wn * 32 + nt * 8 + grp;
                b[nt][0] = Bs[kk + q][nb];
                b[nt][1] = Bs[kk + q + 4][nb];
            }
            #pragma unroll
            for (int mt = 0; mt < 2; mt++)
                #pragma unroll
                for (int nt = 0; nt < 4; nt++)
                    mma_tf32(c[mt][nt], a[mt], b[nt]);
        }
        __syncthreads();
        if (has_next) {
            store_smem();
            __syncthreads();
        }
    }

    #pragma unroll
    for (int mt = 0; mt < 2; mt++) {
        int rg0 = brow + wm * 32 + mt * 16 + grp;
        #pragma unroll
        for (int nt = 0; nt < 4; nt++) {
            int cg = bcol + wn * 32 + nt * 8 + q * 2;
            if (rg0 < M) {
                C[(size_t)rg0 * N + cg]     = c[mt][nt][0];
                C[(size_t)rg0 * N + cg + 1] = c[mt][nt][1];
            }
            if (rg0 + 8 < M) {
                C[(size_t)(rg0 + 8) * N + cg]     = c[mt][nt][2];
                C[(size_t)(rg0 + 8) * N + cg + 1] = c[mt][nt][3];
            }
        }
    }
}

// ---------------- per-(node,head) attention terms s,d ------------------------
template <int HC, int LAYER>
__global__ void sd_kernel(const float* __restrict__ a_src,
                          const float* __restrict__ a_dst)
{
    int gw = blockIdx.x * (blockDim.x >> 5) + (threadIdx.x >> 5);
    int lane = threadIdx.x & 31;
    if (gw >= N_NODES * HEADS) return;
    int n = gw >> 2;
    int hh = gw & 3;
    const int CH = HEADS * HC;
    const float* h = (LAYER == 1) ? g_h1 : g_h2;
    float sv = 0.f, dv = 0.f;
    #pragma unroll
    for (int c = lane; c < HC; c += 32) {
        float hv = h[(size_t)n * CH + hh * HC + c];
        sv += hv * a_src[hh * HC + c];
        dv += hv * a_dst[hh * HC + c];
    }
    #pragma unroll
    for (int off = 16; off > 0; off >>= 1) {
        sv += __shfl_down_sync(0xffffffff, sv, off);
        dv += __shfl_down_sync(0xffffffff, dv, off);
    }
    if (lane == 0) {
        if (LAYER == 1) { g_s1[gw] = sv; g_d1[gw] = dv; }
        else            { g_s2[gw] = sv; g_d2[gw] = dv; }
    }
}

// ---------------- fused GAT softmax-aggregate v3 (R6 winner) ------------------
// Single pass, no segment-max. Block per node, thread per channel.
// Edge weights computed once into smem; gather loop unrolled x4 for MLP.
// LAYER==2 fuses the global mean-pool accumulation (atomics) in the epilogue.
#define CHUNK 128
template <int HC, int LAYER>
__global__ void agg_kernel(const float* __restrict__ bias,
                           const int* __restrict__ batch)
{
    constexpr int CH = HEADS * HC;
    constexpr int T = CH;

    __shared__ int   s_src[CHUNK];
    __shared__ float s_w[CHUNK * HEADS];

    int n = blockIdx.x;
    int tid = threadIdx.x;
    int hh = tid / HC;

    const float* h = (LAYER == 1) ? g_h1 : g_h2;
    const float* s = (LAYER == 1) ? g_s1 : g_s2;
    const float* d = (LAYER == 1) ? g_d1 : g_d2;

    int beg = g_indptr[n], end = g_indptr[n + 1];

    float4 dn4 = *(const float4*)&d[n * 4];
    float4 ss4 = *(const float4*)&s[n * 4];
    const float* dnp = (const float*)&dn4;
    const float* ssp = (const float*)&ss4;

    float e_self = lrelu(ssp[hh] + dnp[hh]);
    float w_self = __expf(e_self);
    float denom = w_self;
    float acc = w_self * h[(size_t)n * CH + tid];

    for (int base = beg; base < end; base += CHUNK) {
        int cnt = min(CHUNK, end - base);
        __syncthreads();
        if (tid < cnt) {
            int src = g_esrc[base + tid];
            float4 s4 = *(const float4*)&s[src * 4];
            float4 w4;
            w4.x = __expf(lrelu(s4.x + dn4.x));
            w4.y = __expf(lrelu(s4.y + dn4.y));
            w4.z = __expf(lrelu(s4.z + dn4.z));
            w4.w = __expf(lrelu(s4.w + dn4.w));
            s_src[tid] = src;
            *(float4*)&s_w[tid * 4] = w4;
        }
        __syncthreads();
        int e = 0;
        for (; e + 4 <= cnt; e += 4) {
            int i0 = s_src[e], i1 = s_src[e + 1], i2 = s_src[e + 2], i3 = s_src[e + 3];
            float w0 = s_w[(e)     * 4 + hh];
            float w1 = s_w[(e + 1) * 4 + hh];
            float w2 = s_w[(e + 2) * 4 + hh];
            float w3 = s_w[(e + 3) * 4 + hh];
            float h0 = h[(size_t)i0 * CH + tid];
            float h1 = h[(size_t)i1 * CH + tid];
            float h2 = h[(size_t)i2 * CH + tid];
            float h3 = h[(size_t)i3 * CH + tid];
            denom += (w0 + w1) + (w2 + w3);
            acc += w0 * h0;
            acc += w1 * h1;
            acc += w2 * h2;
            acc += w3 * h3;
        }
        for (; e < cnt; e++) {
            int src = s_src[e];
            float w = s_w[e * 4 + hh];
            denom += w;
            acc += w * h[(size_t)src * CH + tid];
        }
    }

    float v = fmaxf(acc / (denom + 1e-16f) + bias[tid], 0.f);
    if (LAYER == 1) {
        g_h1gat[(size_t)n * CH + tid] = v;
    } else {
        int gb = batch[n];
        atomicAdd(&g_sums[gb * CH2 + tid], v);
        if (tid == 0) atomicAdd(&g_counts[gb], 1);
    }
}

// ---------------- final logits + softmax --------------------------------------
__global__ void final_kernel(const float* __restrict__ Wout,
                             const float* __restrict__ bout,
                             float* __restrict__ out)
{
    int g = threadIdx.x;
    if (g >= N_GRAPHS) return;
    float cnt = fmaxf((float)g_counts[g], 1.0f);
    float l0 = bout[0], l1 = bout[1];
    for (int c = 0; c < CH2; c++) {
        float p = g_sums[g * CH2 + c] / cnt;
        l0 += p * Wout[c * 2 + 0];
        l1 += p * Wout[c * 2 + 1];
    }
    float mx = fmaxf(l0, l1);
    float e0 = expf(l0 - mx), e1 = expf(l1 - mx);
    float inv = 1.f / (e0 + e1);
    out[g * 2 + 0] = e0 * inv;
    out[g * 2 + 1] = e1 * inv;
}

// ---------------- launch -------------------------------------------------------
extern "C" void kernel_launch(void* const* d_in, const int* in_sizes, int n_in,
                              void* d_out, int out_size) {
    const float* x      = (const float*)d_in[0];
    const int*   ei     = (const int*)d_in[1];
    const int*   batch  = (const int*)d_in[2];
    const float* W1     = (const float*)d_in[3];
    const float* a_src1 = (const float*)d_in[4];
    const float* a_dst1 = (const float*)d_in[5];
    const float* b1     = (const float*)d_in[6];
    const float* W2     = (const float*)d_in[7];
    const float* a_src2 = (const float*)d_in[8];
    const float* a_dst2 = (const float*)d_in[9];
    const float* b2     = (const float*)d_in[10];
    const float* Wout   = (const float*)d_in[11];
    const float* bout   = (const float*)d_in[12];
    float* out = (float*)d_out;

    zero_kernel<<<(N_NODES + 255) / 256, 256>>>();

    count_kernel<<<(N_EDGES + 255) / 256, 256>>>(ei);
    scan1_kernel<<<NB, SCAN_B>>>();
    scan2_kernel<<<1, 64>>>();
    scan3_kernel<<<(N_NODES + 255) / 256, 256>>>();
    scatter_kernel<<<(N_EDGES + 255) / 256, 256>>>(ei);

    {
        dim3 grid(CH1 / BN, (N_NODES + BM - 1) / BM);
        gemm_tf32_kernel<1><<<grid, 256>>>(x, W1);
    }
    sd_kernel<HID_CH, 1><<<(N_NODES * HEADS * 32 + 255) / 256, 256>>>(a_src1, a_dst1);
    agg_kernel<HID_CH, 1><<<N_NODES, CH1>>>(b1, batch);

    {
        dim3 grid(CH2 / BN, (N_NODES + BM - 1) / BM);
        gemm_tf32_kernel<2><<<grid, 256>>>(nullptr, W2);
    }
    sd_kernel<OUT_CH, 2><<<(N_NODES * HEADS * 32 + 255) / 256, 256>>>(a_src2, a_dst2);
    agg_kernel<OUT_CH, 2><<<N_NODES, CH2>>>(b2, batch);

    final_kernel<<<1, 64>>>(Wout, bout, out);
}

// round 9
// speedup vs baseline: 2.3873x; 1.2174x over previous
#include <cuda_runtime.h>
#include <cuda_bf16.h>
#include <math.h>
#include <stdint.h>

#define N_NODES 50000
#define N_EDGES 800000
#define N_GRAPHS 64
#define HEADS 4
#define IN_CH 128
#define HID_CH 64
#define OUT_CH 32
#define CH1 (HEADS*HID_CH)   // 256
#define CH2 (HEADS*OUT_CH)   // 128

#define SCAN_B 1024
#define NB ((N_NODES + SCAN_B - 1) / SCAN_B)   // 49

// ---------------- scratch (device globals) ----------------------------------
__device__ __nv_bfloat162 g_h1b[N_NODES * CH1 / 2];      // x@W1 (bf16)
__device__ __nv_bfloat162 g_h1gatb[N_NODES * CH1 / 2];   // layer1 out (bf16)
__device__ __nv_bfloat162 g_h2b[N_NODES * CH2 / 2];      // h1gat@W2 (bf16)
__device__ float g_s1[N_NODES * HEADS], g_d1[N_NODES * HEADS];
__device__ float g_s2[N_NODES * HEADS], g_d2[N_NODES * HEADS];
__device__ int   g_cnt[N_NODES];
__device__ int   g_cursor[N_NODES];
__device__ int   g_incl[N_NODES];
__device__ int   g_indptr[N_NODES + 1];
__device__ int   g_esrc[N_EDGES];
__device__ int   g_blocksums[NB];
__device__ float g_sums[N_GRAPHS * CH2];
__device__ int   g_counts[N_GRAPHS];

__device__ __forceinline__ float lrelu(float x) {
    return x > 0.f ? x : 0.2f * x;
}

// ---------------- zero scratch ----------------------------------------------
__global__ void zero_kernel() {
    int i = blockIdx.x * blockDim.x + threadIdx.x;
    if (i < N_NODES) { g_cnt[i] = 0; g_cursor[i] = 0; }
    if (i < N_GRAPHS * CH2) g_sums[i] = 0.f;
    if (i < N_GRAPHS) g_counts[i] = 0;
}

// ---------------- CSR build --------------------------------------------------
__global__ void count_kernel(const int* __restrict__ ei) {
    int e = blockIdx.x * blockDim.x + threadIdx.x;
    if (e < N_EDGES) atomicAdd(&g_cnt[ei[N_EDGES + e]], 1);
}

__global__ void scan1_kernel() {
    __shared__ int sh[SCAN_B];
    int i = blockIdx.x * SCAN_B + threadIdx.x;
    int v = (i < N_NODES) ? g_cnt[i] : 0;
    sh[threadIdx.x] = v;
    __syncthreads();
    #pragma unroll
    for (int off = 1; off < SCAN_B; off <<= 1) {
        int t = (threadIdx.x >= off) ? sh[threadIdx.x - off] : 0;
        __syncthreads();
        sh[threadIdx.x] += t;
        __syncthreads();
    }
    if (i < N_NODES) g_incl[i] = sh[threadIdx.x];
    if (threadIdx.x == SCAN_B - 1) g_blocksums[blockIdx.x] = sh[SCAN_B - 1];
}

__global__ void scan2_kernel() {
    __shared__ int sh[64];
    int t = threadIdx.x;
    int v = (t < NB) ? g_blocksums[t] : 0;
    sh[t] = v;
    __syncthreads();
    #pragma unroll
    for (int off = 1; off < 64; off <<= 1) {
        int u = (t >= off) ? sh[t - off] : 0;
        __syncthreads();
        sh[t] += u;
        __syncthreads();
    }
    if (t < NB) g_blocksums[t] = sh[t] - v;   // exclusive
}

__global__ void scan3_kernel() {
    int i = blockIdx.x * blockDim.x + threadIdx.x;
    if (i < N_NODES) g_indptr[i + 1] = g_incl[i] + g_blocksums[i / SCAN_B];
    if (i == 0) g_indptr[0] = 0;
}

__global__ void scatter_kernel(const int* __restrict__ ei) {
    int e = blockIdx.x * blockDim.x + threadIdx.x;
    if (e < N_EDGES) {
        int s = ei[e];
        int d = ei[N_EDGES + e];
        int pos = g_indptr[d] + atomicAdd(&g_cursor[d], 1);
        g_esrc[pos] = s;
    }
}

// ---------------- tf32 tensor-core GEMM --------------------------------------
#define BM 128
#define BN 64
#define BK 32
#define ASTRIDE 36
#define BSTRIDE 72

__device__ __forceinline__ float cvt_tf32(float x) {
    uint32_t r;
    asm("cvt.rna.tf32.f32 %0, %1;" : "=r"(r) : "f"(x));
    return __uint_as_float(r);
}

__device__ __forceinline__ void mma_tf32(float c[4], const float a[4], const float b[2]) {
    asm volatile(
        "mma.sync.aligned.m16n8k8.row.col.f32.tf32.tf32.f32 "
        "{%0,%1,%2,%3}, {%4,%5,%6,%7}, {%8,%9}, {%0,%1,%2,%3};"
        : "+f"(c[0]), "+f"(c[1]), "+f"(c[2]), "+f"(c[3])
        : "r"(__float_as_uint(a[0])), "r"(__float_as_uint(a[1])),
          "r"(__float_as_uint(a[2])), "r"(__float_as_uint(a[3])),
          "r"(__float_as_uint(b[0])), "r"(__float_as_uint(b[1])));
}

// LAYER=1: g_h1b = x(fp32) @ W1.  LAYER=2: g_h2b = g_h1gatb(bf16) @ W2.
template <int LAYER>
__global__ __launch_bounds__(256) void gemm_tf32_kernel(
    const float* __restrict__ Ain, const float* __restrict__ B)
{
    constexpr int N = (LAYER == 1) ? CH1 : CH2;
    constexpr int K = (LAYER == 1) ? IN_CH : CH1;
    const int M = N_NODES;
    __nv_bfloat162* Cb = (LAYER == 1) ? g_h1b : g_h2b;

    __shared__ float As[BM][ASTRIDE];
    __shared__ float Bs[BK][BSTRIDE];

    int tid = threadIdx.x;
    int brow = blockIdx.y * BM;
    int bcol = blockIdx.x * BN;
    int wid = tid >> 5, lane = tid & 31;
    int wm = wid & 3, wn = wid >> 2;
    int grp = lane >> 2;
    int q = lane & 3;

    // fp32 A-load indices (layer 1)
    int ar = tid >> 3;
    int ac4 = (tid & 7) << 2;
    // bf16 A-load indices (layer 2): 8 elems (uint4) per load, 2 loads
    int ar2 = tid >> 2;            // 0..63
    int ac8 = (tid & 3) << 3;      // 0,8,16,24
    // B-load indices
    int bc4 = (tid & 15) << 2;
    int br0 = tid >> 4;

    float4 ra[4];
    uint4  rab[2];
    float4 rb[2];

    auto load_regs = [&](int k0) {
        if (LAYER == 1) {
            #pragma unroll
            for (int i = 0; i < 4; i++) {
                int gr = brow + ar + i * 32;
                ra[i] = make_float4(0.f, 0.f, 0.f, 0.f);
                if (gr < M) ra[i] = *(const float4*)&Ain[(size_t)gr * K + k0 + ac4];
            }
        } else {
            #pragma unroll
            for (int i = 0; i < 2; i++) {
                int gr = brow + ar2 + i * 64;
                rab[i] = make_uint4(0, 0, 0, 0);
                if (gr < M)
                    rab[i] = *(const uint4*)&g_h1gatb[((size_t)gr * K + k0 + ac8) >> 1];
            }
        }
        #pragma unroll
        for (int i = 0; i < 2; i++) {
            int r = br0 + i * 16;
            rb[i] = *(const float4*)&B[(size_t)(k0 + r) * N + bcol + bc4];
        }
    };
    auto store_smem = [&]() {
        if (LAYER == 1) {
            #pragma unroll
            for (int i = 0; i < 4; i++) {
                int r = ar + i * 32;
                As[r][ac4 + 0] = cvt_tf32(ra[i].x);
                As[r][ac4 + 1] = cvt_tf32(ra[i].y);
                As[r][ac4 + 2] = cvt_tf32(ra[i].z);
                As[r][ac4 + 3] = cvt_tf32(ra[i].w);
            }
        } else {
            #pragma unroll
            for (int i = 0; i < 2; i++) {
                int r = ar2 + i * 64;
                const __nv_bfloat162* p = (const __nv_bfloat162*)&rab[i];
                #pragma unroll
                for (int j = 0; j < 4; j++) {
                    float2 f = __bfloat1622float2(p[j]);   // bf16 subset of tf32: exact
                    As[r][ac8 + j * 2 + 0] = f.x;
                    As[r][ac8 + j * 2 + 1] = f.y;
                }
            }
        }
        #pragma unroll
        for (int i = 0; i < 2; i++) {
            int r = br0 + i * 16;
            Bs[r][bc4 + 0] = cvt_tf32(rb[i].x);
            Bs[r][bc4 + 1] = cvt_tf32(rb[i].y);
            Bs[r][bc4 + 2] = cvt_tf32(rb[i].z);
            Bs[r][bc4 + 3] = cvt_tf32(rb[i].w);
        }
    };

    float c[2][4][4];
    #pragma unroll
    for (int mt = 0; mt < 2; mt++)
        #pragma unroll
        for (int nt = 0; nt < 4; nt++)
            #pragma unroll
            for (int r = 0; r < 4; r++) c[mt][nt][r] = 0.f;

    load_regs(0);
    store_smem();
    __syncthreads();

    for (int k0 = 0; k0 < K; k0 += BK) {
        bool has_next = (k0 + BK) < K;
        if (has_next) load_regs(k0 + BK);

        #pragma unroll
        for (int ks = 0; ks < BK / 8; ks++) {
            int kk = ks * 8;
            float a[2][4], b[4][2];
            #pragma unroll
            for (int mt = 0; mt < 2; mt++) {
                int mb = wm * 32 + mt * 16 + grp;
                a[mt][0] = As[mb][kk + q];
                a[mt][1] = As[mb + 8][kk + q];
                a[mt][2] = As[mb][kk + q + 4];
                a[mt][3] = As[mb + 8][kk + q + 4];
            }
            #pragma unroll
            for (int nt = 0; nt < 4; nt++) {
                int nb = wn * 32 + nt * 8 + grp;
                b[nt][0] = Bs[kk + q][nb];
                b[nt][1] = Bs[kk + q + 4][nb];
            }
            #pragma unroll
            for (int mt = 0; mt < 2; mt++)
                #pragma unroll
                for (int nt = 0; nt < 4; nt++)
                    mma_tf32(c[mt][nt], a[mt], b[nt]);
        }
        __syncthreads();
        if (has_next) {
            store_smem();
            __syncthreads();
        }
    }

    // epilogue: pack fp32 pairs -> bf162
    #pragma unroll
    for (int mt = 0; mt < 2; mt++) {
        int rg0 = brow + wm * 32 + mt * 16 + grp;
        #pragma unroll
        for (int nt = 0; nt < 4; nt++) {
            int cg = bcol + wn * 32 + nt * 8 + q * 2;
            if (rg0 < M)
                Cb[((size_t)rg0 * N + cg) >> 1] =
                    __floats2bfloat162_rn(c[mt][nt][0], c[mt][nt][1]);
            if (rg0 + 8 < M)
                Cb[((size_t)(rg0 + 8) * N + cg) >> 1] =
                    __floats2bfloat162_rn(c[mt][nt][2], c[mt][nt][3]);
        }
    }
}

// ---------------- per-(node,head) attention terms s,d ------------------------
// One warp per (node, head); channels as bf162 pairs.
template <int HC, int LAYER>
__global__ void sd_kernel(const float* __restrict__ a_src,
                          const float* __restrict__ a_dst)
{
    int gw = blockIdx.x * (blockDim.x >> 5) + (threadIdx.x >> 5);
    int lane = threadIdx.x & 31;
    if (gw >= N_NODES * HEADS) return;
    int n = gw >> 2;
    int hh = gw & 3;
    constexpr int CH = HEADS * HC;
    const __nv_bfloat162* hb = (LAYER == 1) ? g_h1b : g_h2b;
    float sv = 0.f, dv = 0.f;
    #pragma unroll
    for (int p = lane; p < HC / 2; p += 32) {
        float2 hv = __bfloat1622float2(hb[(size_t)n * (CH / 2) + hh * (HC / 2) + p]);
        int c = hh * HC + 2 * p;
        sv += hv.x * a_src[c] + hv.y * a_src[c + 1];
        dv += hv.x * a_dst[c] + hv.y * a_dst[c + 1];
    }
    #pragma unroll
    for (int off = 16; off > 0; off >>= 1) {
        sv += __shfl_down_sync(0xffffffff, sv, off);
        dv += __shfl_down_sync(0xffffffff, dv, off);
    }
    if (lane == 0) {
        if (LAYER == 1) { g_s1[gw] = sv; g_d1[gw] = dv; }
        else            { g_s2[gw] = sv; g_d2[gw] = dv; }
    }
}

// ---------------- fused GAT softmax-aggregate (bf16 gathers) ------------------
// Block per node, thread per channel-PAIR (bf162). No segment-max.
// LAYER==2 fuses the global mean-pool accumulation.
template <int HC, int LAYER>
__global__ void agg_kernel(const float* __restrict__ bias,
                           const int* __restrict__ batch)
{
    constexpr int CH = HEADS * HC;
    constexpr int T = CH / 2;          // threads: 128 (L1) / 64 (L2)
    constexpr int CHUNK = T;

    __shared__ int   s_src[CHUNK];
    __shared__ float s_w[CHUNK * HEADS];

    int n = blockIdx.x;
    int tid = threadIdx.x;
    int hh = tid / (HC / 2);

    const __nv_bfloat162* hb = (LAYER == 1) ? g_h1b : g_h2b;
    const float* s = (LAYER == 1) ? g_s1 : g_s2;
    const float* d = (LAYER == 1) ? g_d1 : g_d2;

    int beg = g_indptr[n], end = g_indptr[n + 1];

    float4 dn4 = *(const float4*)&d[n * 4];
    float4 ss4 = *(const float4*)&s[n * 4];
    const float* dnp = (const float*)&dn4;
    const float* ssp = (const float*)&ss4;

    float w_self = __expf(lrelu(ssp[hh] + dnp[hh]));
    float denom = w_self;
    float2 hvs = __bfloat1622float2(hb[(size_t)n * T + tid]);
    float acc0 = w_self * hvs.x;
    float acc1 = w_self * hvs.y;

    for (int base = beg; base < end; base += CHUNK) {
        int cnt = min(CHUNK, end - base);
        __syncthreads();
        if (tid < cnt) {
            int src = g_esrc[base + tid];
            float4 s4 = *(const float4*)&s[src * 4];
            float4 w4;
            w4.x = __expf(lrelu(s4.x + dn4.x));
            w4.y = __expf(lrelu(s4.y + dn4.y));
            w4.z = __expf(lrelu(s4.z + dn4.z));
            w4.w = __expf(lrelu(s4.w + dn4.w));
            s_src[tid] = src;
            *(float4*)&s_w[tid * 4] = w4;
        }
        __syncthreads();
        int e = 0;
        for (; e + 4 <= cnt; e += 4) {
            int i0 = s_src[e], i1 = s_src[e + 1], i2 = s_src[e + 2], i3 = s_src[e + 3];
            float w0 = s_w[(e)     * 4 + hh];
            float w1 = s_w[(e + 1) * 4 + hh];
            float w2 = s_w[(e + 2) * 4 + hh];
            float w3 = s_w[(e + 3) * 4 + hh];
            float2 h0 = __bfloat1622float2(hb[(size_t)i0 * T + tid]);
            float2 h1 = __bfloat1622float2(hb[(size_t)i1 * T + tid]);
            float2 h2 = __bfloat1622float2(hb[(size_t)i2 * T + tid]);
            float2 h3 = __bfloat1622float2(hb[(size_t)i3 * T + tid]);
            denom += (w0 + w1) + (w2 + w3);
            acc0 += w0 * h0.x; acc1 += w0 * h0.y;
            acc0 += w1 * h1.x; acc1 += w1 * h1.y;
            acc0 += w2 * h2.x; acc1 += w2 * h2.y;
            acc0 += w3 * h3.x; acc1 += w3 * h3.y;
        }
        for (; e < cnt; e++) {
            int src = s_src[e];
            float w = s_w[e * 4 + hh];
            float2 hv = __bfloat1622float2(hb[(size_t)src * T + tid]);
            denom += w;
            acc0 += w * hv.x;
            acc1 += w * hv.y;
        }
    }

    float inv = 1.f / (denom + 1e-16f);
    float v0 = fmaxf(acc0 * inv + bias[2 * tid],     0.f);
    float v1 = fmaxf(acc1 * inv + bias[2 * tid + 1], 0.f);
    if (LAYER == 1) {
        g_h1gatb[(size_t)n * T + tid] = __floats2bfloat162_rn(v0, v1);
    } else {
        int gb = batch[n];
        atomicAdd(&g_sums[gb * CH2 + 2 * tid],     v0);
        atomicAdd(&g_sums[gb * CH2 + 2 * tid + 1], v1);
        if (tid == 0) atomicAdd(&g_counts[gb], 1);
    }
}

// ---------------- final logits + softmax --------------------------------------
__global__ void final_kernel(const float* __restrict__ Wout,
                             const float* __restrict__ bout,
                             float* __restrict__ out)
{
    int g = threadIdx.x;
    if (g >= N_GRAPHS) return;
    float cnt = fmaxf((float)g_counts[g], 1.0f);
    float l0 = bout[0], l1 = bout[1];
    for (int c = 0; c < CH2; c++) {
        float p = g_sums[g * CH2 + c] / cnt;
        l0 += p * Wout[c * 2 + 0];
        l1 += p * Wout[c * 2 + 1];
    }
    float mx = fmaxf(l0, l1);
    float e0 = expf(l0 - mx), e1 = expf(l1 - mx);
    float inv = 1.f / (e0 + e1);
    out[g * 2 + 0] = e0 * inv;
    out[g * 2 + 1] = e1 * inv;
}

// ---------------- launch -------------------------------------------------------
extern "C" void kernel_launch(void* const* d_in, const int* in_sizes, int n_in,
                              void* d_out, int out_size) {
    const float* x      = (const float*)d_in[0];
    const int*   ei     = (const int*)d_in[1];
    const int*   batch  = (const int*)d_in[2];
    const float* W1     = (const float*)d_in[3];
    const float* a_src1 = (const float*)d_in[4];
    const float* a_dst1 = (const float*)d_in[5];
    const float* b1     = (const float*)d_in[6];
    const float* W2     = (const float*)d_in[7];
    const float* a_src2 = (const float*)d_in[8];
    const float* a_dst2 = (const float*)d_in[9];
    const float* b2     = (const float*)d_in[10];
    const float* Wout   = (const float*)d_in[11];
    const float* bout   = (const float*)d_in[12];
    float* out = (float*)d_out;

    zero_kernel<<<(N_NODES + 255) / 256, 256>>>();

    count_kernel<<<(N_EDGES + 255) / 256, 256>>>(ei);
    scan1_kernel<<<NB, SCAN_B>>>();
    scan2_kernel<<<1, 64>>>();
    scan3_kernel<<<(N_NODES + 255) / 256, 256>>>();
    scatter_kernel<<<(N_EDGES + 255) / 256, 256>>>(ei);

    {
        dim3 grid(CH1 / BN, (N_NODES + BM - 1) / BM);
        gemm_tf32_kernel<1><<<grid, 256>>>(x, W1);
    }
    sd_kernel<HID_CH, 1><<<(N_NODES * HEADS * 32 + 255) / 256, 256>>>(a_src1, a_dst1);
    agg_kernel<HID_CH, 1><<<N_NODES, CH1 / 2>>>(b1, batch);

    {
        dim3 grid(CH2 / BN, (N_NODES + BM - 1) / BM);
        gemm_tf32_kernel<2><<<grid, 256>>>(nullptr, W2);
    }
    sd_kernel<OUT_CH, 2><<<(N_NODES * HEADS * 32 + 255) / 256, 256>>>(a_src2, a_dst2);
    agg_kernel<OUT_CH, 2><<<N_NODES, CH2 / 2>>>(b2, batch);

    final_kernel<<<1, 64>>>(Wout, bout, out);
}

// round 10
// speedup vs baseline: 2.6640x; 1.1159x over previous
#include <cuda_runtime.h>
#include <cuda_bf16.h>
#include <math.h>
#include <stdint.h>

#define N_NODES 50000
#define N_EDGES 800000
#define N_GRAPHS 64
#define HEADS 4
#define IN_CH 128
#define HID_CH 64
#define OUT_CH 32
#define CH1 (HEADS*HID_CH)   // 256
#define CH2 (HEADS*OUT_CH)   // 128

#define SCAN_B 1024
#define NB ((N_NODES + SCAN_B - 1) / SCAN_B)   // 49

// ---------------- scratch (device globals) ----------------------------------
__device__ __nv_bfloat162 g_h1b[N_NODES * CH1 / 2];
__device__ __nv_bfloat162 g_h1gatb[N_NODES * CH1 / 2];
__device__ __nv_bfloat162 g_h2b[N_NODES * CH2 / 2];
__device__ float g_s1[N_NODES * HEADS], g_d1[N_NODES * HEADS];
__device__ float g_s2[N_NODES * HEADS], g_d2[N_NODES * HEADS];
__device__ int   g_cnt[N_NODES];
__device__ int   g_cursor[N_NODES];
__device__ int   g_incl[N_NODES];
__device__ int   g_indptr[N_NODES + 1];
__device__ int   g_esrc[N_EDGES];
__device__ int   g_blocksums[NB];
__device__ float g_sums[N_GRAPHS * CH2];
__device__ int   g_counts[N_GRAPHS];

__device__ __forceinline__ float lrelu(float x) {
    return x > 0.f ? x : 0.2f * x;
}

// ---------------- zero scratch ----------------------------------------------
__global__ void zero_kernel() {
    int i = blockIdx.x * blockDim.x + threadIdx.x;
    if (i < N_NODES) { g_cnt[i] = 0; g_cursor[i] = 0; }
    if (i < N_GRAPHS * CH2) g_sums[i] = 0.f;
    if (i < N_GRAPHS) g_counts[i] = 0;
}

// ---------------- CSR build --------------------------------------------------
__global__ void count_kernel(const int* __restrict__ ei) {
    int e = blockIdx.x * blockDim.x + threadIdx.x;
    if (e < N_EDGES) atomicAdd(&g_cnt[ei[N_EDGES + e]], 1);
}

__global__ void scan1_kernel() {
    __shared__ int sh[SCAN_B];
    int i = blockIdx.x * SCAN_B + threadIdx.x;
    int v = (i < N_NODES) ? g_cnt[i] : 0;
    sh[threadIdx.x] = v;
    __syncthreads();
    #pragma unroll
    for (int off = 1; off < SCAN_B; off <<= 1) {
        int t = (threadIdx.x >= off) ? sh[threadIdx.x - off] : 0;
        __syncthreads();
        sh[threadIdx.x] += t;
        __syncthreads();
    }
    if (i < N_NODES) g_incl[i] = sh[threadIdx.x];
    if (threadIdx.x == SCAN_B - 1) g_blocksums[blockIdx.x] = sh[SCAN_B - 1];
}

__global__ void scan2_kernel() {
    __shared__ int sh[64];
    int t = threadIdx.x;
    int v = (t < NB) ? g_blocksums[t] : 0;
    sh[t] = v;
    __syncthreads();
    #pragma unroll
    for (int off = 1; off < 64; off <<= 1) {
        int u = (t >= off) ? sh[t - off] : 0;
        __syncthreads();
        sh[t] += u;
        __syncthreads();
    }
    if (t < NB) g_blocksums[t] = sh[t] - v;   // exclusive
}

__global__ void scan3_kernel() {
    int i = blockIdx.x * blockDim.x + threadIdx.x;
    if (i < N_NODES) g_indptr[i + 1] = g_incl[i] + g_blocksums[i / SCAN_B];
    if (i == 0) g_indptr[0] = 0;
}

__global__ void scatter_kernel(const int* __restrict__ ei) {
    int e = blockIdx.x * blockDim.x + threadIdx.x;
    if (e < N_EDGES) {
        int s = ei[e];
        int d = ei[N_EDGES + e];
        int pos = g_indptr[d] + atomicAdd(&g_cursor[d], 1);
        g_esrc[pos] = s;
    }
}

// ---------------- tf32 tensor-core GEMM + fused s,d epilogue ------------------
#define BM 128
#define BN 64
#define BK 32
#define ASTRIDE 36
#define BSTRIDE 72

__device__ __forceinline__ float cvt_tf32(float x) {
    uint32_t r;
    asm("cvt.rna.tf32.f32 %0, %1;" : "=r"(r) : "f"(x));
    return __uint_as_float(r);
}

__device__ __forceinline__ void mma_tf32(float c[4], const float a[4], const float b[2]) {
    asm volatile(
        "mma.sync.aligned.m16n8k8.row.col.f32.tf32.tf32.f32 "
        "{%0,%1,%2,%3}, {%4,%5,%6,%7}, {%8,%9}, {%0,%1,%2,%3};"
        : "+f"(c[0]), "+f"(c[1]), "+f"(c[2]), "+f"(c[3])
        : "r"(__float_as_uint(a[0])), "r"(__float_as_uint(a[1])),
          "r"(__float_as_uint(a[2])), "r"(__float_as_uint(a[3])),
          "r"(__float_as_uint(b[0])), "r"(__float_as_uint(b[1])));
}

// LAYER=1: g_h1b = x(fp32) @ W1, HC=64 (block col == head), s,d -> g_s1/g_d1
// LAYER=2: g_h2b = g_h1gatb(bf16) @ W2, HC=32 (warp col == head), s,d -> g_s2/g_d2
template <int LAYER>
__global__ __launch_bounds__(256) void gemm_tf32_kernel(
    const float* __restrict__ Ain, const float* __restrict__ B,
    const float* __restrict__ a_src, const float* __restrict__ a_dst)
{
    constexpr int N = (LAYER == 1) ? CH1 : CH2;
    constexpr int K = (LAYER == 1) ? IN_CH : CH1;
    const int M = N_NODES;
    __nv_bfloat162* Cb = (LAYER == 1) ? g_h1b : g_h2b;
    float* gs = (LAYER == 1) ? g_s1 : g_s2;
    float* gd = (LAYER == 1) ? g_d1 : g_d2;

    __shared__ float As[BM][ASTRIDE];
    __shared__ float Bs[BK][BSTRIDE];

    int tid = threadIdx.x;
    int brow = blockIdx.y * BM;
    int bcol = blockIdx.x * BN;
    int wid = tid >> 5, lane = tid & 31;
    int wm = wid & 3, wn = wid >> 2;
    int grp = lane >> 2;
    int q = lane & 3;

    int ar = tid >> 3;
    int ac4 = (tid & 7) << 2;
    int ar2 = tid >> 2;
    int ac8 = (tid & 3) << 3;
    int bc4 = (tid & 15) << 2;
    int br0 = tid >> 4;

    float4 ra[4];
    uint4  rab[2];
    float4 rb[2];

    auto load_regs = [&](int k0) {
        if (LAYER == 1) {
            #pragma unroll
            for (int i = 0; i < 4; i++) {
                int gr = brow + ar + i * 32;
                ra[i] = make_float4(0.f, 0.f, 0.f, 0.f);
                if (gr < M) ra[i] = *(const float4*)&Ain[(size_t)gr * K + k0 + ac4];
            }
        } else {
            #pragma unroll
            for (int i = 0; i < 2; i++) {
                int gr = brow + ar2 + i * 64;
                rab[i] = make_uint4(0, 0, 0, 0);
                if (gr < M)
                    rab[i] = *(const uint4*)&g_h1gatb[((size_t)gr * K + k0 + ac8) >> 1];
            }
        }
        #pragma unroll
        for (int i = 0; i < 2; i++) {
            int r = br0 + i * 16;
            rb[i] = *(const float4*)&B[(size_t)(k0 + r) * N + bcol + bc4];
        }
    };
    auto store_smem = [&]() {
        if (LAYER == 1) {
            #pragma unroll
            for (int i = 0; i < 4; i++) {
                int r = ar + i * 32;
                As[r][ac4 + 0] = cvt_tf32(ra[i].x);
                As[r][ac4 + 1] = cvt_tf32(ra[i].y);
                As[r][ac4 + 2] = cvt_tf32(ra[i].z);
                As[r][ac4 + 3] = cvt_tf32(ra[i].w);
            }
        } else {
            #pragma unroll
            for (int i = 0; i < 2; i++) {
                int r = ar2 + i * 64;
                const __nv_bfloat162* p = (const __nv_bfloat162*)&rab[i];
                #pragma unroll
                for (int j = 0; j < 4; j++) {
                    float2 f = __bfloat1622float2(p[j]);
                    As[r][ac8 + j * 2 + 0] = f.x;
                    As[r][ac8 + j * 2 + 1] = f.y;
                }
            }
        }
        #pragma unroll
        for (int i = 0; i < 2; i++) {
            int r = br0 + i * 16;
            Bs[r][bc4 + 0] = cvt_tf32(rb[i].x);
            Bs[r][bc4 + 1] = cvt_tf32(rb[i].y);
            Bs[r][bc4 + 2] = cvt_tf32(rb[i].z);
            Bs[r][bc4 + 3] = cvt_tf32(rb[i].w);
        }
    };

    float c[2][4][4];
    #pragma unroll
    for (int mt = 0; mt < 2; mt++)
        #pragma unroll
        for (int nt = 0; nt < 4; nt++)
            #pragma unroll
            for (int r = 0; r < 4; r++) c[mt][nt][r] = 0.f;

    load_regs(0);
    store_smem();
    __syncthreads();

    for (int k0 = 0; k0 < K; k0 += BK) {
        bool has_next = (k0 + BK) < K;
        if (has_next) load_regs(k0 + BK);

        #pragma unroll
        for (int ks = 0; ks < BK / 8; ks++) {
            int kk = ks * 8;
            float a[2][4], b[4][2];
            #pragma unroll
            for (int mt = 0; mt < 2; mt++) {
                int mb = wm * 32 + mt * 16 + grp;
                a[mt][0] = As[mb][kk + q];
                a[mt][1] = As[mb + 8][kk + q];
                a[mt][2] = As[mb][kk + q + 4];
                a[mt][3] = As[mb + 8][kk + q + 4];
            }
            #pragma unroll
            for (int nt = 0; nt < 4; nt++) {
                int nb = wn * 32 + nt * 8 + grp;
                b[nt][0] = Bs[kk + q][nb];
                b[nt][1] = Bs[kk + q + 4][nb];
            }
            #pragma unroll
            for (int mt = 0; mt < 2; mt++)
                #pragma unroll
                for (int nt = 0; nt < 4; nt++)
                    mma_tf32(c[mt][nt], a[mt], b[nt]);
        }
        __syncthreads();
        if (has_next) {
            store_smem();
            __syncthreads();
        }
    }

    // ---- epilogue 1: pack fp32 -> bf162 store of h ----
    #pragma unroll
    for (int mt = 0; mt < 2; mt++) {
        int rg0 = brow + wm * 32 + mt * 16 + grp;
        #pragma unroll
        for (int nt = 0; nt < 4; nt++) {
            int cg = bcol + wn * 32 + nt * 8 + q * 2;
            if (rg0 < M)
                Cb[((size_t)rg0 * N + cg) >> 1] =
                    __floats2bfloat162_rn(c[mt][nt][0], c[mt][nt][1]);
            if (rg0 + 8 < M)
                Cb[((size_t)(rg0 + 8) * N + cg) >> 1] =
                    __floats2bfloat162_rn(c[mt][nt][2], c[mt][nt][3]);
        }
    }

    // ---- epilogue 2: fused s,d = <h, a_src/a_dst> per (row, head) ----
    constexpr int HC = (LAYER == 1) ? HID_CH : OUT_CH;
    // per-thread partials: [mt][half] for s and d
    float ps[2][2] = {{0.f, 0.f}, {0.f, 0.f}};
    float pd[2][2] = {{0.f, 0.f}, {0.f, 0.f}};
    {
        // head this thread's columns belong to
        int hh = (LAYER == 1) ? (bcol / HID_CH) : (bcol / OUT_CH + wn);
        #pragma unroll
        for (int nt = 0; nt < 4; nt++) {
            int ch = (LAYER == 1) ? (wn * 32 + nt * 8 + q * 2) : (nt * 8 + q * 2);
            float a0 = a_src[hh * HC + ch], a1 = a_src[hh * HC + ch + 1];
            float d0 = a_dst[hh * HC + ch], d1 = a_dst[hh * HC + ch + 1];
            #pragma unroll
            for (int mt = 0; mt < 2; mt++) {
                ps[mt][0] += c[mt][nt][0] * a0 + c[mt][nt][1] * a1;
                pd[mt][0] += c[mt][nt][0] * d0 + c[mt][nt][1] * d1;
                ps[mt][1] += c[mt][nt][2] * a0 + c[mt][nt][3] * a1;
                pd[mt][1] += c[mt][nt][2] * d0 + c[mt][nt][3] * d1;
            }
        }
        // reduce over q (4 lanes): v += down2; v += down1 (read at q==0)
        #pragma unroll
        for (int mt = 0; mt < 2; mt++)
            #pragma unroll
            for (int hf = 0; hf < 2; hf++) {
                ps[mt][hf] += __shfl_down_sync(0xffffffff, ps[mt][hf], 2);
                ps[mt][hf] += __shfl_down_sync(0xffffffff, ps[mt][hf], 1);
                pd[mt][hf] += __shfl_down_sync(0xffffffff, pd[mt][hf], 2);
                pd[mt][hf] += __shfl_down_sync(0xffffffff, pd[mt][hf], 1);
            }

        if (LAYER == 2) {
            // warp tile == one head: direct store from q==0 lanes
            if (q == 0) {
                #pragma unroll
                for (int mt = 0; mt < 2; mt++)
                    #pragma unroll
                    for (int hf = 0; hf < 2; hf++) {
                        int grow = brow + wm * 32 + mt * 16 + grp + hf * 8;
                        if (grow < M) {
                            gs[grow * HEADS + hh] = ps[mt][hf];
                            gd[grow * HEADS + hh] = pd[mt][hf];
                        }
                    }
            }
        } else {
            // block tile == one head: combine the two n-warps via smem
            float* red = &As[0][0];   // reuse (>=512 floats available)
            if (q == 0) {
                #pragma unroll
                for (int mt = 0; mt < 2; mt++)
                    #pragma unroll
                    for (int hf = 0; hf < 2; hf++) {
                        int row = wm * 32 + mt * 16 + grp + hf * 8;
                        red[wn * 256 + row * 2 + 0] = ps[mt][hf];
                        red[wn * 256 + row * 2 + 1] = pd[mt][hf];
                    }
            }
            __syncthreads();
            if (tid < 128) {
                int grow = brow + tid;
                if (grow < M) {
                    float sv = red[tid * 2]     + red[256 + tid * 2];
                    float dv = red[tid * 2 + 1] + red[256 + tid * 2 + 1];
                    gs[grow * HEADS + hh] = sv;
                    gd[grow * HEADS + hh] = dv;
                }
            }
        }
    }
}

// ---------------- fused GAT softmax-aggregate (bf16 gathers, unroll 8) --------
template <int HC, int LAYER>
__global__ void agg_kernel(const float* __restrict__ bias,
                           const int* __restrict__ batch)
{
    constexpr int CH = HEADS * HC;
    constexpr int T = CH / 2;          // threads: 128 (L1) / 64 (L2)
    constexpr int CHUNK = T;

    __shared__ int   s_src[CHUNK];
    __shared__ float s_w[CHUNK * HEADS];

    int n = blockIdx.x;
    int tid = threadIdx.x;
    int hh = tid / (HC / 2);

    const __nv_bfloat162* hb = (LAYER == 1) ? g_h1b : g_h2b;
    const float* s = (LAYER == 1) ? g_s1 : g_s2;
    const float* d = (LAYER == 1) ? g_d1 : g_d2;

    int beg = g_indptr[n], end = g_indptr[n + 1];

    float4 dn4 = *(const float4*)&d[n * 4];
    float4 ss4 = *(const float4*)&s[n * 4];
    const float* dnp = (const float*)&dn4;
    const float* ssp = (const float*)&ss4;

    float w_self = __expf(lrelu(ssp[hh] + dnp[hh]));
    float denom = w_self;
    float2 hvs = __bfloat1622float2(hb[(size_t)n * T + tid]);
    float acc0 = w_self * hvs.x;
    float acc1 = w_self * hvs.y;

    for (int base = beg; base < end; base += CHUNK) {
        int cnt = min(CHUNK, end - base);
        __syncthreads();
        if (tid < cnt) {
            int src = g_esrc[base + tid];
            float4 s4 = *(const float4*)&s[src * 4];
            float4 w4;
            w4.x = __expf(lrelu(s4.x + dn4.x));
            w4.y = __expf(lrelu(s4.y + dn4.y));
            w4.z = __expf(lrelu(s4.z + dn4.z));
            w4.w = __expf(lrelu(s4.w + dn4.w));
            s_src[tid] = src;
            *(float4*)&s_w[tid * 4] = w4;
        }
        __syncthreads();
        int e = 0;
        for (; e + 8 <= cnt; e += 8) {
            int   idx[8];
            float w[8];
            float2 hv[8];
            #pragma unroll
            for (int u = 0; u < 8; u++) {
                idx[u] = s_src[e + u];
                w[u] = s_w[(e + u) * 4 + hh];
            }
            #pragma unroll
            for (int u = 0; u < 8; u++)
                hv[u] = __bfloat1622float2(hb[(size_t)idx[u] * T + tid]);
            #pragma unroll
            for (int u = 0; u < 8; u++) {
                denom += w[u];
                acc0 += w[u] * hv[u].x;
                acc1 += w[u] * hv[u].y;
            }
        }
        for (; e < cnt; e++) {
            int src = s_src[e];
            float w = s_w[e * 4 + hh];
            float2 hv = __bfloat1622float2(hb[(size_t)src * T + tid]);
            denom += w;
            acc0 += w * hv.x;
            acc1 += w * hv.y;
        }
    }

    float inv = 1.f / (denom + 1e-16f);
    float v0 = fmaxf(acc0 * inv + bias[2 * tid],     0.f);
    float v1 = fmaxf(acc1 * inv + bias[2 * tid + 1], 0.f);
    if (LAYER == 1) {
        g_h1gatb[(size_t)n * T + tid] = __floats2bfloat162_rn(v0, v1);
    } else {
        int gb = batch[n];
        atomicAdd(&g_sums[gb * CH2 + 2 * tid],     v0);
        atomicAdd(&g_sums[gb * CH2 + 2 * tid + 1], v1);
        if (tid == 0) atomicAdd(&g_counts[gb], 1);
    }
}

// ---------------- final logits + softmax --------------------------------------
__global__ void final_kernel(const float* __restrict__ Wout,
                             const float* __restrict__ bout,
                             float* __restrict__ out)
{
    int g = threadIdx.x;
    if (g >= N_GRAPHS) return;
    float cnt = fmaxf((float)g_counts[g], 1.0f);
    float l0 = bout[0], l1 = bout[1];
    for (int c = 0; c < CH2; c++) {
        float p = g_sums[g * CH2 + c] / cnt;
        l0 += p * Wout[c * 2 + 0];
        l1 += p * Wout[c * 2 + 1];
    }
    float mx = fmaxf(l0, l1);
    float e0 = expf(l0 - mx), e1 = expf(l1 - mx);
    float inv = 1.f / (e0 + e1);
    out[g * 2 + 0] = e0 * inv;
    out[g * 2 + 1] = e1 * inv;
}

// ---------------- launch -------------------------------------------------------
extern "C" void kernel_launch(void* const* d_in, const int* in_sizes, int n_in,
                              void* d_out, int out_size) {
    const float* x      = (const float*)d_in[0];
    const int*   ei     = (const int*)d_in[1];
    const int*   batch  = (const int*)d_in[2];
    const float* W1     = (const float*)d_in[3];
    const float* a_src1 = (const float*)d_in[4];
    const float* a_dst1 = (const float*)d_in[5];
    const float* b1     = (const float*)d_in[6];
    const float* W2     = (const float*)d_in[7];
    const float* a_src2 = (const float*)d_in[8];
    const float* a_dst2 = (const float*)d_in[9];
    const float* b2     = (const float*)d_in[10];
    const float* Wout   = (const float*)d_in[11];
    const float* bout   = (const float*)d_in[12];
    float* out = (float*)d_out;

    zero_kernel<<<(N_NODES + 255) / 256, 256>>>();

    count_kernel<<<(N_EDGES + 255) / 256, 256>>>(ei);
    scan1_kernel<<<NB, SCAN_B>>>();
    scan2_kernel<<<1, 64>>>();
    scan3_kernel<<<(N_NODES + 255) / 256, 256>>>();
    scatter_kernel<<<(N_EDGES + 255) / 256, 256>>>(ei);

    {
        dim3 grid(CH1 / BN, (N_NODES + BM - 1) / BM);
        gemm_tf32_kernel<1><<<grid, 256>>>(x, W1, a_src1, a_dst1);
    }
    agg_kernel<HID_CH, 1><<<N_NODES, CH1 / 2>>>(b1, batch);

    {
        dim3 grid(CH2 / BN, (N_NODES + BM - 1) / BM);
        gemm_tf32_kernel<2><<<grid, 256>>>(nullptr, W2, a_src2, a_dst2);
    }
    agg_kernel<OUT_CH, 2><<<N_NODES, CH2 / 2>>>(b2, batch);

    final_kernel<<<1, 64>>>(Wout, bout, out);
}

// round 11
// speedup vs baseline: 2.7203x; 1.0211x over previous
#include <cuda_runtime.h>
#include <cuda_bf16.h>
#include <math.h>
#include <stdint.h>

#define N_NODES 50000
#define N_EDGES 800000
#define N_GRAPHS 64
#define HEADS 4
#define IN_CH 128
#define HID_CH 64
#define OUT_CH 32
#define CH1 (HEADS*HID_CH)   // 256
#define CH2 (HEADS*OUT_CH)   // 128

#define SCAN_B 1024
#define NB ((N_NODES + SCAN_B - 1) / SCAN_B)   // 49

// ---------------- scratch (device globals) ----------------------------------
__device__ __nv_bfloat162 g_h1b[N_NODES * CH1 / 2];
__device__ __nv_bfloat162 g_h1gatb[N_NODES * CH1 / 2];
__device__ __nv_bfloat162 g_h2b[N_NODES * CH2 / 2];
__device__ float g_s1[N_NODES * HEADS], g_d1[N_NODES * HEADS];
__device__ float g_s2[N_NODES * HEADS], g_d2[N_NODES * HEADS];
__device__ int   g_cnt[N_NODES];
__device__ int   g_incl[N_NODES];
__device__ int   g_indptr[N_NODES + 1];
__device__ int   g_esrc[N_EDGES];
__device__ int   g_blocksums[NB];
__device__ float g_sums[N_GRAPHS * CH2];
__device__ int   g_counts[N_GRAPHS];

__device__ __forceinline__ float lrelu(float x) {
    return x > 0.f ? x : 0.2f * x;
}

// ---------------- zero scratch ----------------------------------------------
__global__ void zero_kernel() {
    int i = blockIdx.x * blockDim.x + threadIdx.x;
    if (i < N_NODES) g_cnt[i] = 0;
    if (i < N_GRAPHS * CH2) g_sums[i] = 0.f;
    if (i < N_GRAPHS) g_counts[i] = 0;
}

// ---------------- CSR build --------------------------------------------------
__global__ void count_kernel(const int* __restrict__ ei) {
    int e = blockIdx.x * blockDim.x + threadIdx.x;
    if (e < N_EDGES) atomicAdd(&g_cnt[ei[N_EDGES + e]], 1);
}

__global__ void scan1_kernel() {
    __shared__ int sh[SCAN_B];
    int i = blockIdx.x * SCAN_B + threadIdx.x;
    int v = (i < N_NODES) ? g_cnt[i] : 0;
    sh[threadIdx.x] = v;
    __syncthreads();
    #pragma unroll
    for (int off = 1; off < SCAN_B; off <<= 1) {
        int t = (threadIdx.x >= off) ? sh[threadIdx.x - off] : 0;
        __syncthreads();
        sh[threadIdx.x] += t;
        __syncthreads();
    }
    if (i < N_NODES) g_incl[i] = sh[threadIdx.x];
    if (threadIdx.x == SCAN_B - 1) g_blocksums[blockIdx.x] = sh[SCAN_B - 1];
}

__global__ void scan2_kernel() {
    __shared__ int sh[64];
    int t = threadIdx.x;
    int v = (t < NB) ? g_blocksums[t] : 0;
    sh[t] = v;
    __syncthreads();
    #pragma unroll
    for (int off = 1; off < 64; off <<= 1) {
        int u = (t >= off) ? sh[t - off] : 0;
        __syncthreads();
        sh[t] += u;
        __syncthreads();
    }
    if (t < NB) g_blocksums[t] = sh[t] - v;   // exclusive
}

__global__ void scan3_kernel() {
    int i = blockIdx.x * blockDim.x + threadIdx.x;
    if (i < N_NODES) g_indptr[i + 1] = g_incl[i] + g_blocksums[i / SCAN_B];
    if (i == 0) g_indptr[0] = 0;
}

// scatter uses atomicSub on g_cnt (holds degree after count): pos = indptr[d] + remaining-1
__global__ void scatter_kernel(const int* __restrict__ ei) {
    int e = blockIdx.x * blockDim.x + threadIdx.x;
    if (e < N_EDGES) {
        int s = ei[e];
        int d = ei[N_EDGES + e];
        int pos = g_indptr[d] + atomicSub(&g_cnt[d], 1) - 1;
        g_esrc[pos] = s;
    }
}

// ---------------- tf32 tensor-core GEMM + fused s,d epilogue ------------------
#define BM 128
#define BN 64
#define BK 32
#define ASTRIDE 36
#define BSTRIDE 72

__device__ __forceinline__ float cvt_tf32(float x) {
    uint32_t r;
    asm("cvt.rna.tf32.f32 %0, %1;" : "=r"(r) : "f"(x));
    return __uint_as_float(r);
}

__device__ __forceinline__ void mma_tf32(float c[4], const float a[4], const float b[2]) {
    asm volatile(
        "mma.sync.aligned.m16n8k8.row.col.f32.tf32.tf32.f32 "
        "{%0,%1,%2,%3}, {%4,%5,%6,%7}, {%8,%9}, {%0,%1,%2,%3};"
        : "+f"(c[0]), "+f"(c[1]), "+f"(c[2]), "+f"(c[3])
        : "r"(__float_as_uint(a[0])), "r"(__float_as_uint(a[1])),
          "r"(__float_as_uint(a[2])), "r"(__float_as_uint(a[3])),
          "r"(__float_as_uint(b[0])), "r"(__float_as_uint(b[1])));
}

// LAYER=1: g_h1b = x(fp32) @ W1, s,d -> g_s1/g_d1
// LAYER=2: g_h2b = g_h1gatb(bf16) @ W2, s,d -> g_s2/g_d2
template <int LAYER>
__global__ __launch_bounds__(256) void gemm_tf32_kernel(
    const float* __restrict__ Ain, const float* __restrict__ B,
    const float* __restrict__ a_src, const float* __restrict__ a_dst)
{
    constexpr int N = (LAYER == 1) ? CH1 : CH2;
    constexpr int K = (LAYER == 1) ? IN_CH : CH1;
    const int M = N_NODES;
    __nv_bfloat162* Cb = (LAYER == 1) ? g_h1b : g_h2b;
    float* gs = (LAYER == 1) ? g_s1 : g_s2;
    float* gd = (LAYER == 1) ? g_d1 : g_d2;

    __shared__ float As[BM][ASTRIDE];
    __shared__ float Bs[BK][BSTRIDE];

    int tid = threadIdx.x;
    int brow = blockIdx.y * BM;
    int bcol = blockIdx.x * BN;
    int wid = tid >> 5, lane = tid & 31;
    int wm = wid & 3, wn = wid >> 2;
    int grp = lane >> 2;
    int q = lane & 3;

    int ar = tid >> 3;
    int ac4 = (tid & 7) << 2;
    int ar2 = tid >> 2;
    int ac8 = (tid & 3) << 3;
    int bc4 = (tid & 15) << 2;
    int br0 = tid >> 4;

    float4 ra[4];
    uint4  rab[2];
    float4 rb[2];

    auto load_regs = [&](int k0) {
        if (LAYER == 1) {
            #pragma unroll
            for (int i = 0; i < 4; i++) {
                int gr = brow + ar + i * 32;
                ra[i] = make_float4(0.f, 0.f, 0.f, 0.f);
                if (gr < M) ra[i] = *(const float4*)&Ain[(size_t)gr * K + k0 + ac4];
            }
        } else {
            #pragma unroll
            for (int i = 0; i < 2; i++) {
                int gr = brow + ar2 + i * 64;
                rab[i] = make_uint4(0, 0, 0, 0);
                if (gr < M)
                    rab[i] = *(const uint4*)&g_h1gatb[((size_t)gr * K + k0 + ac8) >> 1];
            }
        }
        #pragma unroll
        for (int i = 0; i < 2; i++) {
            int r = br0 + i * 16;
            rb[i] = *(const float4*)&B[(size_t)(k0 + r) * N + bcol + bc4];
        }
    };
    auto store_smem = [&]() {
        if (LAYER == 1) {
            #pragma unroll
            for (int i = 0; i < 4; i++) {
                int r = ar + i * 32;
                As[r][ac4 + 0] = cvt_tf32(ra[i].x);
                As[r][ac4 + 1] = cvt_tf32(ra[i].y);
                As[r][ac4 + 2] = cvt_tf32(ra[i].z);
                As[r][ac4 + 3] = cvt_tf32(ra[i].w);
            }
        } else {
            #pragma unroll
            for (int i = 0; i < 2; i++) {
                int r = ar2 + i * 64;
                const __nv_bfloat162* p = (const __nv_bfloat162*)&rab[i];
                #pragma unroll
                for (int j = 0; j < 4; j++) {
                    float2 f = __bfloat1622float2(p[j]);
                    As[r][ac8 + j * 2 + 0] = f.x;
                    As[r][ac8 + j * 2 + 1] = f.y;
                }
            }
        }
        #pragma unroll
        for (int i = 0; i < 2; i++) {
            int r = br0 + i * 16;
            Bs[r][bc4 + 0] = cvt_tf32(rb[i].x);
            Bs[r][bc4 + 1] = cvt_tf32(rb[i].y);
            Bs[r][bc4 + 2] = cvt_tf32(rb[i].z);
            Bs[r][bc4 + 3] = cvt_tf32(rb[i].w);
        }
    };

    float c[2][4][4];
    #pragma unroll
    for (int mt = 0; mt < 2; mt++)
        #pragma unroll
        for (int nt = 0; nt < 4; nt++)
            #pragma unroll
            for (int r = 0; r < 4; r++) c[mt][nt][r] = 0.f;

    load_regs(0);
    store_smem();
    __syncthreads();

    for (int k0 = 0; k0 < K; k0 += BK) {
        bool has_next = (k0 + BK) < K;
        if (has_next) load_regs(k0 + BK);

        #pragma unroll
        for (int ks = 0; ks < BK / 8; ks++) {
            int kk = ks * 8;
            float a[2][4], b[4][2];
            #pragma unroll
            for (int mt = 0; mt < 2; mt++) {
                int mb = wm * 32 + mt * 16 + grp;
                a[mt][0] = As[mb][kk + q];
                a[mt][1] = As[mb + 8][kk + q];
                a[mt][2] = As[mb][kk + q + 4];
                a[mt][3] = As[mb + 8][kk + q + 4];
            }
            #pragma unroll
            for (int nt = 0; nt < 4; nt++) {
                int nb = wn * 32 + nt * 8 + grp;
                b[nt][0] = Bs[kk + q][nb];
                b[nt][1] = Bs[kk + q + 4][nb];
            }
            #pragma unroll
            for (int mt = 0; mt < 2; mt++)
                #pragma unroll
                for (int nt = 0; nt < 4; nt++)
                    mma_tf32(c[mt][nt], a[mt], b[nt]);
        }
        __syncthreads();
        if (has_next) {
            store_smem();
            __syncthreads();
        }
    }

    // ---- epilogue 1: pack fp32 -> bf162 store of h ----
    #pragma unroll
    for (int mt = 0; mt < 2; mt++) {
        int rg0 = brow + wm * 32 + mt * 16 + grp;
        #pragma unroll
        for (int nt = 0; nt < 4; nt++) {
            int cg = bcol + wn * 32 + nt * 8 + q * 2;
            if (rg0 < M)
                Cb[((size_t)rg0 * N + cg) >> 1] =
                    __floats2bfloat162_rn(c[mt][nt][0], c[mt][nt][1]);
            if (rg0 + 8 < M)
                Cb[((size_t)(rg0 + 8) * N + cg) >> 1] =
                    __floats2bfloat162_rn(c[mt][nt][2], c[mt][nt][3]);
        }
    }

    // ---- epilogue 2: fused s,d per (row, head) ----
    constexpr int HC = (LAYER == 1) ? HID_CH : OUT_CH;
    float ps[2][2] = {{0.f, 0.f}, {0.f, 0.f}};
    float pd[2][2] = {{0.f, 0.f}, {0.f, 0.f}};
    {
        int hh = (LAYER == 1) ? (bcol / HID_CH) : (bcol / OUT_CH + wn);
        #pragma unroll
        for (int nt = 0; nt < 4; nt++) {
            int ch = (LAYER == 1) ? (wn * 32 + nt * 8 + q * 2) : (nt * 8 + q * 2);
            float a0 = a_src[hh * HC + ch], a1 = a_src[hh * HC + ch + 1];
            float d0 = a_dst[hh * HC + ch], d1 = a_dst[hh * HC + ch + 1];
            #pragma unroll
            for (int mt = 0; mt < 2; mt++) {
                ps[mt][0] += c[mt][nt][0] * a0 + c[mt][nt][1] * a1;
                pd[mt][0] += c[mt][nt][0] * d0 + c[mt][nt][1] * d1;
                ps[mt][1] += c[mt][nt][2] * a0 + c[mt][nt][3] * a1;
                pd[mt][1] += c[mt][nt][2] * d0 + c[mt][nt][3] * d1;
            }
        }
        #pragma unroll
        for (int mt = 0; mt < 2; mt++)
            #pragma unroll
            for (int hf = 0; hf < 2; hf++) {
                ps[mt][hf] += __shfl_down_sync(0xffffffff, ps[mt][hf], 2);
                ps[mt][hf] += __shfl_down_sync(0xffffffff, ps[mt][hf], 1);
                pd[mt][hf] += __shfl_down_sync(0xffffffff, pd[mt][hf], 2);
                pd[mt][hf] += __shfl_down_sync(0xffffffff, pd[mt][hf], 1);
            }

        if (LAYER == 2) {
            if (q == 0) {
                #pragma unroll
                for (int mt = 0; mt < 2; mt++)
                    #pragma unroll
                    for (int hf = 0; hf < 2; hf++) {
                        int grow = brow + wm * 32 + mt * 16 + grp + hf * 8;
                        if (grow < M) {
                            gs[grow * HEADS + hh] = ps[mt][hf];
                            gd[grow * HEADS + hh] = pd[mt][hf];
                        }
                    }
            }
        } else {
            float* red = &As[0][0];
            if (q == 0) {
                #pragma unroll
                for (int mt = 0; mt < 2; mt++)
                    #pragma unroll
                    for (int hf = 0; hf < 2; hf++) {
                        int row = wm * 32 + mt * 16 + grp + hf * 8;
                        red[wn * 256 + row * 2 + 0] = ps[mt][hf];
                        red[wn * 256 + row * 2 + 1] = pd[mt][hf];
                    }
            }
            __syncthreads();
            if (tid < 128) {
                int grow = brow + tid;
                if (grow < M) {
                    float sv = red[tid * 2]     + red[256 + tid * 2];
                    float dv = red[tid * 2 + 1] + red[256 + tid * 2 + 1];
                    gs[grow * HEADS + hh] = sv;
                    gd[grow * HEADS + hh] = dv;
                }
            }
        }
    }
}

// ---------------- warp-per-node GAT softmax-aggregate -------------------------
// One warp per node. Lane owns PPL bf162 channel-pairs at p = lane + 32*i.
// head(p) = p / (HC/2). No smem, no block syncs. No segment-max (safe range).
// LAYER==2 fuses the global mean-pool accumulation.
template <int LAYER>
__global__ __launch_bounds__(256) void agg_kernel(const float* __restrict__ bias,
                                                  const int* __restrict__ batch)
{
    constexpr int CH = (LAYER == 1) ? CH1 : CH2;
    constexpr int PAIRS = CH / 2;        // 128 / 64
    constexpr int PPL = PAIRS / 32;      // 4 / 2
    constexpr int HCP = (LAYER == 1) ? (HID_CH / 2) : (OUT_CH / 2);  // 32 / 16

    int n = blockIdx.x * (blockDim.x >> 5) + (threadIdx.x >> 5);
    if (n >= N_NODES) return;
    int lane = threadIdx.x & 31;

    const __nv_bfloat162* hb = (LAYER == 1) ? g_h1b : g_h2b;
    const float* s = (LAYER == 1) ? g_s1 : g_s2;
    const float* d = (LAYER == 1) ? g_d1 : g_d2;

    float4 dn4 = *(const float4*)&d[n * 4];
    float4 ss4 = *(const float4*)&s[n * 4];

    // head index of each lane-pair (layer1: = i; layer2: lane/16 + 2i)
    int headof[PPL];
    #pragma unroll
    for (int i = 0; i < PPL; i++) headof[i] = (lane + 32 * i) / HCP;

    // self-loop
    float wself[HEADS];
    wself[0] = __expf(lrelu(ss4.x + dn4.x));
    wself[1] = __expf(lrelu(ss4.y + dn4.y));
    wself[2] = __expf(lrelu(ss4.z + dn4.z));
    wself[3] = __expf(lrelu(ss4.w + dn4.w));
    float denom[HEADS] = { wself[0], wself[1], wself[2], wself[3] };

    float acc[PPL][2];
    #pragma unroll
    for (int i = 0; i < PPL; i++) {
        float2 hv = __bfloat1622float2(hb[(size_t)n * PAIRS + lane + 32 * i]);
        float w = wself[headof[i]];
        acc[i][0] = w * hv.x;
        acc[i][1] = w * hv.y;
    }

    int beg = g_indptr[n], end = g_indptr[n + 1];
    for (int base = beg; base < end; base += 32) {
        int m = min(32, end - base);
        int srcl = 0;
        float4 wl = make_float4(0.f, 0.f, 0.f, 0.f);
        if (lane < m) {
            srcl = g_esrc[base + lane];
            float4 s4 = *(const float4*)&s[srcl * 4];
            wl.x = __expf(lrelu(s4.x + dn4.x));
            wl.y = __expf(lrelu(s4.y + dn4.y));
            wl.z = __expf(lrelu(s4.z + dn4.z));
            wl.w = __expf(lrelu(s4.w + dn4.w));
        }
        #pragma unroll 4
        for (int j = 0; j < m; j++) {
            int src = __shfl_sync(0xffffffffu, srcl, j);
            float w0 = __shfl_sync(0xffffffffu, wl.x, j);
            float w1 = __shfl_sync(0xffffffffu, wl.y, j);
            float w2 = __shfl_sync(0xffffffffu, wl.z, j);
            float w3 = __shfl_sync(0xffffffffu, wl.w, j);
            float wh[HEADS] = { w0, w1, w2, w3 };
            #pragma unroll
            for (int i = 0; i < PPL; i++) {
                float2 hv = __bfloat1622float2(hb[(size_t)src * PAIRS + lane + 32 * i]);
                float w = wh[headof[i]];
                acc[i][0] += w * hv.x;
                acc[i][1] += w * hv.y;
            }
            denom[0] += w0; denom[1] += w1; denom[2] += w2; denom[3] += w3;
        }
    }

    float inv[HEADS];
    #pragma unroll
    for (int k = 0; k < HEADS; k++) inv[k] = 1.f / (denom[k] + 1e-16f);

    if (LAYER == 1) {
        #pragma unroll
        for (int i = 0; i < PPL; i++) {
            int p = lane + 32 * i;
            float v0 = fmaxf(acc[i][0] * inv[headof[i]] + bias[2 * p],     0.f);
            float v1 = fmaxf(acc[i][1] * inv[headof[i]] + bias[2 * p + 1], 0.f);
            g_h1gatb[(size_t)n * PAIRS + p] = __floats2bfloat162_rn(v0, v1);
        }
    } else {
        int gb = batch[n];
        #pragma unroll
        for (int i = 0; i < PPL; i++) {
            int p = lane + 32 * i;
            float v0 = fmaxf(acc[i][0] * inv[headof[i]] + bias[2 * p],     0.f);
            float v1 = fmaxf(acc[i][1] * inv[headof[i]] + bias[2 * p + 1], 0.f);
            atomicAdd(&g_sums[gb * CH2 + 2 * p],     v0);
            atomicAdd(&g_sums[gb * CH2 + 2 * p + 1], v1);
        }
        if (lane == 0) atomicAdd(&g_counts[gb], 1);
    }
}

// ---------------- final logits + softmax --------------------------------------
__global__ void final_kernel(const float* __restrict__ Wout,
                             const float* __restrict__ bout,
                             float* __restrict__ out)
{
    int g = threadIdx.x;
    if (g >= N_GRAPHS) return;
    float cnt = fmaxf((float)g_counts[g], 1.0f);
    float l0 = bout[0], l1 = bout[1];
    for (int c = 0; c < CH2; c++) {
        float p = g_sums[g * CH2 + c] / cnt;
        l0 += p * Wout[c * 2 + 0];
        l1 += p * Wout[c * 2 + 1];
    }
    float mx = fmaxf(l0, l1);
    float e0 = expf(l0 - mx), e1 = expf(l1 - mx);
    float inv = 1.f / (e0 + e1);
    out[g * 2 + 0] = e0 * inv;
    out[g * 2 + 1] = e1 * inv;
}

// ---------------- launch -------------------------------------------------------
extern "C" void kernel_launch(void* const* d_in, const int* in_sizes, int n_in,
                              void* d_out, int out_size) {
    const float* x      = (const float*)d_in[0];
    const int*   ei     = (const int*)d_in[1];
    const int*   batch  = (const int*)d_in[2];
    const float* W1     = (const float*)d_in[3];
    const float* a_src1 = (const float*)d_in[4];
    const float* a_dst1 = (const float*)d_in[5];
    const float* b1     = (const float*)d_in[6];
    const float* W2     = (const float*)d_in[7];
    const float* a_src2 = (const float*)d_in[8];
    const float* a_dst2 = (const float*)d_in[9];
    const float* b2     = (const float*)d_in[10];
    const float* Wout   = (const float*)d_in[11];
    const float* bout   = (const float*)d_in[12];
    float* out = (float*)d_out;

    zero_kernel<<<(N_NODES + 255) / 256, 256>>>();

    count_kernel<<<(N_EDGES + 255) / 256, 256>>>(ei);
    scan1_kernel<<<NB, SCAN_B>>>();
    scan2_kernel<<<1, 64>>>();
    scan3_kernel<<<(N_NODES + 255) / 256, 256>>>();
    scatter_kernel<<<(N_EDGES + 255) / 256, 256>>>(ei);

    {
        dim3 grid(CH1 / BN, (N_NODES + BM - 1) / BM);
        gemm_tf32_kernel<1><<<grid, 256>>>(x, W1, a_src1, a_dst1);
    }
    agg_kernel<1><<<(N_NODES * 32 + 255) / 256, 256>>>(b1, batch);

    {
        dim3 grid(CH2 / BN, (N_NODES + BM - 1) / BM);
        gemm_tf32_kernel<2><<<grid, 256>>>(nullptr, W2, a_src2, a_dst2);
    }
    agg_kernel<2><<<(N_NODES * 32 + 255) / 256, 256>>>(b2, batch);

    final_kernel<<<1, 64>>>(Wout, bout, out);
}

// round 12
// speedup vs baseline: 3.0783x; 1.1316x over previous
#include <cuda_runtime.h>
#include <cuda_bf16.h>
#include <math.h>
#include <stdint.h>

#define N_NODES 50000
#define N_EDGES 800000
#define N_GRAPHS 64
#define HEADS 4
#define IN_CH 128
#define HID_CH 64
#define OUT_CH 32
#define CH1 (HEADS*HID_CH)   // 256
#define CH2 (HEADS*OUT_CH)   // 128

#define SCAN_B 1024
#define NB ((N_NODES + SCAN_B - 1) / SCAN_B)   // 49

// ---------------- scratch (device globals) ----------------------------------
// INVARIANT: g_cnt, g_lsum, g_counts are all-zero at kernel_launch entry.
// (zero-init at load; scatter's atomicSub restores g_cnt; final_kernel
// re-zeroes g_lsum/g_counts after consuming them.)
__device__ __nv_bfloat162 g_h1b[N_NODES * CH1 / 2];
__device__ __nv_bfloat162 g_h1gatb[N_NODES * CH1 / 2];
__device__ __nv_bfloat162 g_h2b[N_NODES * CH2 / 2];
__device__ float g_s1[N_NODES * HEADS], g_d1[N_NODES * HEADS];
__device__ float g_s2[N_NODES * HEADS], g_d2[N_NODES * HEADS];
__device__ int   g_cnt[N_NODES];
__device__ int   g_incl[N_NODES];
__device__ int   g_indptr[N_NODES + 1];
__device__ int   g_esrc[N_EDGES];
__device__ int   g_blocksums[NB];
__device__ float g_lsum[N_GRAPHS * 2];
__device__ int   g_counts[N_GRAPHS];

__device__ __forceinline__ float lrelu(float x) {
    return x > 0.f ? x : 0.2f * x;
}

// ---------------- CSR build --------------------------------------------------
__global__ void count_kernel(const int* __restrict__ ei) {
    int e = blockIdx.x * blockDim.x + threadIdx.x;
    if (e < N_EDGES) atomicAdd(&g_cnt[ei[N_EDGES + e]], 1);
}

__global__ void scan1_kernel() {
    __shared__ int sh[SCAN_B];
    int i = blockIdx.x * SCAN_B + threadIdx.x;
    int v = (i < N_NODES) ? g_cnt[i] : 0;
    sh[threadIdx.x] = v;
    __syncthreads();
    #pragma unroll
    for (int off = 1; off < SCAN_B; off <<= 1) {
        int t = (threadIdx.x >= off) ? sh[threadIdx.x - off] : 0;
        __syncthreads();
        sh[threadIdx.x] += t;
        __syncthreads();
    }
    if (i < N_NODES) g_incl[i] = sh[threadIdx.x];
    if (threadIdx.x == SCAN_B - 1) g_blocksums[blockIdx.x] = sh[SCAN_B - 1];
}

__global__ void scan2_kernel() {
    __shared__ int sh[64];
    int t = threadIdx.x;
    int v = (t < NB) ? g_blocksums[t] : 0;
    sh[t] = v;
    __syncthreads();
    #pragma unroll
    for (int off = 1; off < 64; off <<= 1) {
        int u = (t >= off) ? sh[t - off] : 0;
        __syncthreads();
        sh[t] += u;
        __syncthreads();
    }
    if (t < NB) g_blocksums[t] = sh[t] - v;   // exclusive
}

__global__ void scan3_kernel() {
    int i = blockIdx.x * blockDim.x + threadIdx.x;
    if (i < N_NODES) g_indptr[i + 1] = g_incl[i] + g_blocksums[i / SCAN_B];
    if (i == 0) g_indptr[0] = 0;
}

// scatter: atomicSub on g_cnt (degree after count) -> also restores g_cnt to 0
__global__ void scatter_kernel(const int* __restrict__ ei) {
    int e = blockIdx.x * blockDim.x + threadIdx.x;
    if (e < N_EDGES) {
        int s = ei[e];
        int d = ei[N_EDGES + e];
        int pos = g_indptr[d] + atomicSub(&g_cnt[d], 1) - 1;
        g_esrc[pos] = s;
    }
}

// ---------------- tf32 tensor-core GEMM + fused s,d epilogue ------------------
#define BM 128
#define BN 64
#define BK 32
#define ASTRIDE 36
#define BSTRIDE 72

__device__ __forceinline__ float cvt_tf32(float x) {
    uint32_t r;
    asm("cvt.rna.tf32.f32 %0, %1;" : "=r"(r) : "f"(x));
    return __uint_as_float(r);
}

__device__ __forceinline__ void mma_tf32(float c[4], const float a[4], const float b[2]) {
    asm volatile(
        "mma.sync.aligned.m16n8k8.row.col.f32.tf32.tf32.f32 "
        "{%0,%1,%2,%3}, {%4,%5,%6,%7}, {%8,%9}, {%0,%1,%2,%3};"
        : "+f"(c[0]), "+f"(c[1]), "+f"(c[2]), "+f"(c[3])
        : "r"(__float_as_uint(a[0])), "r"(__float_as_uint(a[1])),
          "r"(__float_as_uint(a[2])), "r"(__float_as_uint(a[3])),
          "r"(__float_as_uint(b[0])), "r"(__float_as_uint(b[1])));
}

template <int LAYER>
__global__ __launch_bounds__(256) void gemm_tf32_kernel(
    const float* __restrict__ Ain, const float* __restrict__ B,
    const float* __restrict__ a_src, const float* __restrict__ a_dst)
{
    constexpr int N = (LAYER == 1) ? CH1 : CH2;
    constexpr int K = (LAYER == 1) ? IN_CH : CH1;
    const int M = N_NODES;
    __nv_bfloat162* Cb = (LAYER == 1) ? g_h1b : g_h2b;
    float* gs = (LAYER == 1) ? g_s1 : g_s2;
    float* gd = (LAYER == 1) ? g_d1 : g_d2;

    __shared__ float As[BM][ASTRIDE];
    __shared__ float Bs[BK][BSTRIDE];

    int tid = threadIdx.x;
    int brow = blockIdx.y * BM;
    int bcol = blockIdx.x * BN;
    int wid = tid >> 5, lane = tid & 31;
    int wm = wid & 3, wn = wid >> 2;
    int grp = lane >> 2;
    int q = lane & 3;

    int ar = tid >> 3;
    int ac4 = (tid & 7) << 2;
    int ar2 = tid >> 2;
    int ac8 = (tid & 3) << 3;
    int bc4 = (tid & 15) << 2;
    int br0 = tid >> 4;

    float4 ra[4];
    uint4  rab[2];
    float4 rb[2];

    auto load_regs = [&](int k0) {
        if (LAYER == 1) {
            #pragma unroll
            for (int i = 0; i < 4; i++) {
                int gr = brow + ar + i * 32;
                ra[i] = make_float4(0.f, 0.f, 0.f, 0.f);
                if (gr < M) ra[i] = *(const float4*)&Ain[(size_t)gr * K + k0 + ac4];
            }
        } else {
            #pragma unroll
            for (int i = 0; i < 2; i++) {
                int gr = brow + ar2 + i * 64;
                rab[i] = make_uint4(0, 0, 0, 0);
                if (gr < M)
                    rab[i] = *(const uint4*)&g_h1gatb[((size_t)gr * K + k0 + ac8) >> 1];
            }
        }
        #pragma unroll
        for (int i = 0; i < 2; i++) {
            int r = br0 + i * 16;
            rb[i] = *(const float4*)&B[(size_t)(k0 + r) * N + bcol + bc4];
        }
    };
    auto store_smem = [&]() {
        if (LAYER == 1) {
            #pragma unroll
            for (int i = 0; i < 4; i++) {
                int r = ar + i * 32;
                As[r][ac4 + 0] = cvt_tf32(ra[i].x);
                As[r][ac4 + 1] = cvt_tf32(ra[i].y);
                As[r][ac4 + 2] = cvt_tf32(ra[i].z);
                As[r][ac4 + 3] = cvt_tf32(ra[i].w);
            }
        } else {
            #pragma unroll
            for (int i = 0; i < 2; i++) {
                int r = ar2 + i * 64;
                const __nv_bfloat162* p = (const __nv_bfloat162*)&rab[i];
                #pragma unroll
                for (int j = 0; j < 4; j++) {
                    float2 f = __bfloat1622float2(p[j]);
                    As[r][ac8 + j * 2 + 0] = f.x;
                    As[r][ac8 + j * 2 + 1] = f.y;
                }
            }
        }
        #pragma unroll
        for (int i = 0; i < 2; i++) {
            int r = br0 + i * 16;
            Bs[r][bc4 + 0] = cvt_tf32(rb[i].x);
            Bs[r][bc4 + 1] = cvt_tf32(rb[i].y);
            Bs[r][bc4 + 2] = cvt_tf32(rb[i].z);
            Bs[r][bc4 + 3] = cvt_tf32(rb[i].w);
        }
    };

    float c[2][4][4];
    #pragma unroll
    for (int mt = 0; mt < 2; mt++)
        #pragma unroll
        for (int nt = 0; nt < 4; nt++)
            #pragma unroll
            for (int r = 0; r < 4; r++) c[mt][nt][r] = 0.f;

    load_regs(0);
    store_smem();
    __syncthreads();

    for (int k0 = 0; k0 < K; k0 += BK) {
        bool has_next = (k0 + BK) < K;
        if (has_next) load_regs(k0 + BK);

        #pragma unroll
        for (int ks = 0; ks < BK / 8; ks++) {
            int kk = ks * 8;
            float a[2][4], b[4][2];
            #pragma unroll
            for (int mt = 0; mt < 2; mt++) {
                int mb = wm * 32 + mt * 16 + grp;
                a[mt][0] = As[mb][kk + q];
                a[mt][1] = As[mb + 8][kk + q];
                a[mt][2] = As[mb][kk + q + 4];
                a[mt][3] = As[mb + 8][kk + q + 4];
            }
            #pragma unroll
            for (int nt = 0; nt < 4; nt++) {
                int nb = wn * 32 + nt * 8 + grp;
                b[nt][0] = Bs[kk + q][nb];
                b[nt][1] = Bs[kk + q + 4][nb];
            }
            #pragma unroll
            for (int mt = 0; mt < 2; mt++)
                #pragma unroll
                for (int nt = 0; nt < 4; nt++)
                    mma_tf32(c[mt][nt], a[mt], b[nt]);
        }
        __syncthreads();
        if (has_next) {
            store_smem();
            __syncthreads();
        }
    }

    // ---- epilogue 1: pack fp32 -> bf162 store of h ----
    #pragma unroll
    for (int mt = 0; mt < 2; mt++) {
        int rg0 = brow + wm * 32 + mt * 16 + grp;
        #pragma unroll
        for (int nt = 0; nt < 4; nt++) {
            int cg = bcol + wn * 32 + nt * 8 + q * 2;
            if (rg0 < M)
                Cb[((size_t)rg0 * N + cg) >> 1] =
                    __floats2bfloat162_rn(c[mt][nt][0], c[mt][nt][1]);
            if (rg0 + 8 < M)
                Cb[((size_t)(rg0 + 8) * N + cg) >> 1] =
                    __floats2bfloat162_rn(c[mt][nt][2], c[mt][nt][3]);
        }
    }

    // ---- epilogue 2: fused s,d per (row, head) ----
    constexpr int HC = (LAYER == 1) ? HID_CH : OUT_CH;
    float ps[2][2] = {{0.f, 0.f}, {0.f, 0.f}};
    float pd[2][2] = {{0.f, 0.f}, {0.f, 0.f}};
    {
        int hh = (LAYER == 1) ? (bcol / HID_CH) : (bcol / OUT_CH + wn);
        #pragma unroll
        for (int nt = 0; nt < 4; nt++) {
            int ch = (LAYER == 1) ? (wn * 32 + nt * 8 + q * 2) : (nt * 8 + q * 2);
            float a0 = a_src[hh * HC + ch], a1 = a_src[hh * HC + ch + 1];
            float d0 = a_dst[hh * HC + ch], d1 = a_dst[hh * HC + ch + 1];
            #pragma unroll
            for (int mt = 0; mt < 2; mt++) {
                ps[mt][0] += c[mt][nt][0] * a0 + c[mt][nt][1] * a1;
                pd[mt][0] += c[mt][nt][0] * d0 + c[mt][nt][1] * d1;
                ps[mt][1] += c[mt][nt][2] * a0 + c[mt][nt][3] * a1;
                pd[mt][1] += c[mt][nt][2] * d0 + c[mt][nt][3] * d1;
            }
        }
        #pragma unroll
        for (int mt = 0; mt < 2; mt++)
            #pragma unroll
            for (int hf = 0; hf < 2; hf++) {
                ps[mt][hf] += __shfl_down_sync(0xffffffff, ps[mt][hf], 2);
                ps[mt][hf] += __shfl_down_sync(0xffffffff, ps[mt][hf], 1);
                pd[mt][hf] += __shfl_down_sync(0xffffffff, pd[mt][hf], 2);
                pd[mt][hf] += __shfl_down_sync(0xffffffff, pd[mt][hf], 1);
            }

        if (LAYER == 2) {
            if (q == 0) {
                #pragma unroll
                for (int mt = 0; mt < 2; mt++)
                    #pragma unroll
                    for (int hf = 0; hf < 2; hf++) {
                        int grow = brow + wm * 32 + mt * 16 + grp + hf * 8;
                        if (grow < M) {
                            gs[grow * HEADS + hh] = ps[mt][hf];
                            gd[grow * HEADS + hh] = pd[mt][hf];
                        }
                    }
            }
        } else {
            float* red = &As[0][0];
            if (q == 0) {
                #pragma unroll
                for (int mt = 0; mt < 2; mt++)
                    #pragma unroll
                    for (int hf = 0; hf < 2; hf++) {
                        int row = wm * 32 + mt * 16 + grp + hf * 8;
                        red[wn * 256 + row * 2 + 0] = ps[mt][hf];
                        red[wn * 256 + row * 2 + 1] = pd[mt][hf];
                    }
            }
            __syncthreads();
            if (tid < 128) {
                int grow = brow + tid;
                if (grow < M) {
                    float sv = red[tid * 2]     + red[256 + tid * 2];
                    float dv = red[tid * 2 + 1] + red[256 + tid * 2 + 1];
                    gs[grow * HEADS + hh] = sv;
                    gd[grow * HEADS + hh] = dv;
                }
            }
        }
    }
}

// ---------------- warp-per-node GAT softmax-aggregate -------------------------
// One warp per node. Lane owns PPL bf162 channel-pairs at p = lane + 32*i.
// LAYER==2: fuses bias+relu, the per-node Wout projection, and the pooled
// logit accumulation (2 atomics per node instead of 128).
template <int LAYER>
__global__ __launch_bounds__(256) void agg_kernel(const float* __restrict__ bias,
                                                  const int* __restrict__ batch,
                                                  const float* __restrict__ Wout)
{
    constexpr int CH = (LAYER == 1) ? CH1 : CH2;
    constexpr int PAIRS = CH / 2;        // 128 / 64
    constexpr int PPL = PAIRS / 32;      // 4 / 2
    constexpr int HCP = (LAYER == 1) ? (HID_CH / 2) : (OUT_CH / 2);  // 32 / 16

    int n = blockIdx.x * (blockDim.x >> 5) + (threadIdx.x >> 5);
    if (n >= N_NODES) return;
    int lane = threadIdx.x & 31;

    const __nv_bfloat162* hb = (LAYER == 1) ? g_h1b : g_h2b;
    const float* s = (LAYER == 1) ? g_s1 : g_s2;
    const float* d = (LAYER == 1) ? g_d1 : g_d2;

    float4 dn4 = *(const float4*)&d[n * 4];
    float4 ss4 = *(const float4*)&s[n * 4];

    int headof[PPL];
    #pragma unroll
    for (int i = 0; i < PPL; i++) headof[i] = (lane + 32 * i) / HCP;

    float wself[HEADS];
    wself[0] = __expf(lrelu(ss4.x + dn4.x));
    wself[1] = __expf(lrelu(ss4.y + dn4.y));
    wself[2] = __expf(lrelu(ss4.z + dn4.z));
    wself[3] = __expf(lrelu(ss4.w + dn4.w));
    float denom[HEADS] = { wself[0], wself[1], wself[2], wself[3] };

    float acc[PPL][2];
    #pragma unroll
    for (int i = 0; i < PPL; i++) {
        float2 hv = __bfloat1622float2(hb[(size_t)n * PAIRS + lane + 32 * i]);
        float w = wself[headof[i]];
        acc[i][0] = w * hv.x;
        acc[i][1] = w * hv.y;
    }

    int beg = g_indptr[n], end = g_indptr[n + 1];
    for (int base = beg; base < end; base += 32) {
        int m = min(32, end - base);
        int srcl = 0;
        float4 wl = make_float4(0.f, 0.f, 0.f, 0.f);
        if (lane < m) {
            srcl = g_esrc[base + lane];
            float4 s4 = *(const float4*)&s[srcl * 4];
            wl.x = __expf(lrelu(s4.x + dn4.x));
            wl.y = __expf(lrelu(s4.y + dn4.y));
            wl.z = __expf(lrelu(s4.z + dn4.z));
            wl.w = __expf(lrelu(s4.w + dn4.w));
        }
        #pragma unroll 4
        for (int j = 0; j < m; j++) {
            int src = __shfl_sync(0xffffffffu, srcl, j);
            float w0 = __shfl_sync(0xffffffffu, wl.x, j);
            float w1 = __shfl_sync(0xffffffffu, wl.y, j);
            float w2 = __shfl_sync(0xffffffffu, wl.z, j);
            float w3 = __shfl_sync(0xffffffffu, wl.w, j);
            float wh[HEADS] = { w0, w1, w2, w3 };
            #pragma unroll
            for (int i = 0; i < PPL; i++) {
                float2 hv = __bfloat1622float2(hb[(size_t)src * PAIRS + lane + 32 * i]);
                float w = wh[headof[i]];
                acc[i][0] += w * hv.x;
                acc[i][1] += w * hv.y;
            }
            denom[0] += w0; denom[1] += w1; denom[2] += w2; denom[3] += w3;
        }
    }

    float inv[HEADS];
    #pragma unroll
    for (int k = 0; k < HEADS; k++) inv[k] = 1.f / (denom[k] + 1e-16f);

    if (LAYER == 1) {
        #pragma unroll
        for (int i = 0; i < PPL; i++) {
            int p = lane + 32 * i;
            float v0 = fmaxf(acc[i][0] * inv[headof[i]] + bias[2 * p],     0.f);
            float v1 = fmaxf(acc[i][1] * inv[headof[i]] + bias[2 * p + 1], 0.f);
            g_h1gatb[(size_t)n * PAIRS + p] = __floats2bfloat162_rn(v0, v1);
        }
    } else {
        // fused bias+relu+Wout projection: per-node 2 logit partials
        float l0 = 0.f, l1 = 0.f;
        #pragma unroll
        for (int i = 0; i < PPL; i++) {
            int p = lane + 32 * i;
            float v0 = fmaxf(acc[i][0] * inv[headof[i]] + bias[2 * p],     0.f);
            float v1 = fmaxf(acc[i][1] * inv[headof[i]] + bias[2 * p + 1], 0.f);
            float4 w = *(const float4*)&Wout[4 * p];   // [2p][0],[2p][1],[2p+1][0],[2p+1][1]
            l0 += v0 * w.x + v1 * w.z;
            l1 += v0 * w.y + v1 * w.w;
        }
        #pragma unroll
        for (int off = 16; off > 0; off >>= 1) {
            l0 += __shfl_down_sync(0xffffffffu, l0, off);
            l1 += __shfl_down_sync(0xffffffffu, l1, off);
        }
        if (lane == 0) {
            int gb = batch[n];
            atomicAdd(&g_lsum[gb * 2 + 0], l0);
            atomicAdd(&g_lsum[gb * 2 + 1], l1);
            atomicAdd(&g_counts[gb], 1);
        }
    }
}

// ---------------- final logits + softmax (+ scratch re-zero) ------------------
__global__ void final_kernel(const float* __restrict__ bout,
                             float* __restrict__ out)
{
    int g = threadIdx.x;
    if (g >= N_GRAPHS) return;
    float cnt = fmaxf((float)g_counts[g], 1.0f);
    float l0 = g_lsum[g * 2 + 0] / cnt + bout[0];
    float l1 = g_lsum[g * 2 + 1] / cnt + bout[1];
    float mx = fmaxf(l0, l1);
    float e0 = expf(l0 - mx), e1 = expf(l1 - mx);
    float inv = 1.f / (e0 + e1);
    out[g * 2 + 0] = e0 * inv;
    out[g * 2 + 1] = e1 * inv;
    // restore the zero-invariant for the next call
    g_lsum[g * 2 + 0] = 0.f;
    g_lsum[g * 2 + 1] = 0.f;
    g_counts[g] = 0;
}

// ---------------- launch -------------------------------------------------------
extern "C" void kernel_launch(void* const* d_in, const int* in_sizes, int n_in,
                              void* d_out, int out_size) {
    const float* x      = (const float*)d_in[0];
    const int*   ei     = (const int*)d_in[1];
    const int*   batch  = (const int*)d_in[2];
    const float* W1     = (const float*)d_in[3];
    const float* a_src1 = (const float*)d_in[4];
    const float* a_dst1 = (const float*)d_in[5];
    const float* b1     = (const float*)d_in[6];
    const float* W2     = (const float*)d_in[7];
    const float* a_src2 = (const float*)d_in[8];
    const float* a_dst2 = (const float*)d_in[9];
    const float* b2     = (const float*)d_in[10];
    const float* Wout   = (const float*)d_in[11];
    const float* bout   = (const float*)d_in[12];
    float* out = (float*)d_out;

    count_kernel<<<(N_EDGES + 255) / 256, 256>>>(ei);
    scan1_kernel<<<NB, SCAN_B>>>();
    scan2_kernel<<<1, 64>>>();
    scan3_kernel<<<(N_NODES + 255) / 256, 256>>>();
    scatter_kernel<<<(N_EDGES + 255) / 256, 256>>>(ei);

    {
        dim3 grid(CH1 / BN, (N_NODES + BM - 1) / BM);
        gemm_tf32_kernel<1><<<grid, 256>>>(x, W1, a_src1, a_dst1);
    }
    agg_kernel<1><<<(N_NODES * 32 + 255) / 256, 256>>>(b1, batch, Wout);

    {
        dim3 grid(CH2 / BN, (N_NODES + BM - 1) / BM);
        gemm_tf32_kernel<2><<<grid, 256>>>(nullptr, W2, a_src2, a_dst2);
    }
    agg_kernel<2><<<(N_NODES * 32 + 255) / 256, 256>>>(b2, batch, Wout);

    final_kernel<<<1, 64>>>(bout, out);
}